// round 3
// baseline (speedup 1.0000x reference)
#include <cuda_runtime.h>
#include <math.h>

#define NTOT 32      // bs * heads
#define CH   64      // head dim
#define LQ   2048
#define LK   2048
#define BQ   32      // q rows per block
#define BK   128     // k cols per chunk
#define NCHK (LK / BK)
#define TPB  256

// Fallback scratch if the harness's d_out does not include the w output.
__device__ float g_w_scratch[(size_t)NTOT * LQ * LK];
__device__ float g_a_scratch[(size_t)NTOT * CH * LQ];

// 0 = uint8/bool, 1 = int32 (0/1), 2 = float32 (0.0/1.0)
__device__ int g_mask_kind;

__global__ void detect_mask_kind_kernel(const unsigned char* __restrict__ m)
{
    if (threadIdx.x != 0 || blockIdx.x != 0) return;
    int nz_r123 = 0;   // nonzero bytes at offset %4 in {1,2,3}
    int nz_r01  = 0;   // nonzero bytes at offset %4 in {0,1}
    int f32_sig = 0;   // bytes at offset %4==3 equal to 0x3F (float 1.0f)
    for (int i = 0; i < 4096; i++) {
        unsigned char b = m[i];
        int r = i & 3;
        if (r != 0 && b != 0) nz_r123++;
        if (r <= 1 && b != 0) nz_r01++;
        if (r == 3 && b == 0x3F) f32_sig++;
    }
    int kind;
    if (nz_r123 == 0)                 kind = 1;  // int32 values 0/1
    else if (nz_r01 == 0 && f32_sig)  kind = 2;  // float32 values 0.0/1.0
    else                              kind = 0;  // byte bool
    g_mask_kind = kind;
}

// Dynamic shared memory layout (bytes)
#define SM_QS   0                         // float [64][32]        = 8192
#define SM_KV   8192                      // float4 [64][32]       = 32768
#define SM_PS   (8192 + 32768)            // float [32][132]       = 16896
#define SM_RM   (SM_PS + 32 * 132 * 4)    // float [32]
#define SM_RI   (SM_RM + 128)             // float [32]
#define SM_TOT  (SM_RI + 128)             // 58368 total

extern "C" __global__ void __launch_bounds__(TPB, 2)
attn_fused_kernel(const float* __restrict__ gq,
                  const float* __restrict__ gk,
                  const float* __restrict__ gv,
                  const void* __restrict__ gmask,
                  float* __restrict__ ga,
                  float* __restrict__ gw)
{
    extern __shared__ char sm[];
    float*  Qs   = (float*)(sm + SM_QS);    // [c][q]  pre-scaled Q tile
    float4* KVs  = (float4*)(sm + SM_KV);   // [c][k/4] K or V chunk
    float*  Ps   = (float*)(sm + SM_PS);    // [q][132] normalized probs chunk
    float*  rowM = (float*)(sm + SM_RM);
    float*  rowI = (float*)(sm + SM_RI);

    const int n     = blockIdx.y;           // head index (0..31)
    const int qbase = blockIdx.x * BQ;
    const int tid   = threadIdx.x;
    const int lane  = tid & 31;
    const int warp  = tid >> 5;             // 8 warps
    const int mkind = g_mask_kind;

    const float* qh = gq + (size_t)n * CH * LQ;
    const float* kh = gk + (size_t)n * CH * LK;
    const float* vh = gv + (size_t)n * CH * LK;
    float* wtile = gw + ((size_t)n * LQ + qbase) * LK;
    const size_t mrow0 = (size_t)(n >> 4) * LQ + qbase;   // mask element-row base

    // ---- Load Q tile (pre-scaled by 1/sqrt(ch)) ----
    #pragma unroll
    for (int e = tid; e < CH * BQ; e += TPB) {
        int c = e >> 5, qi = e & 31;
        Qs[c * BQ + qi] = qh[(size_t)c * LQ + qbase + qi] * 0.125f;
    }
    __syncthreads();

    // ================= Pass 1: S = Q^T K, mask, raw-score write, row stats =================
    float rm[4], rs[4];
    #pragma unroll
    for (int i = 0; i < 4; i++) { rm[i] = -INFINITY; rs[i] = 0.f; }

    for (int cb = 0; cb < NCHK; cb++) {
        const int kb = cb * BK;
        #pragma unroll
        for (int e = tid; e < CH * (BK / 4); e += TPB) {
            int c = e >> 5, k4 = e & 31;
            KVs[c * 32 + k4] = *(const float4*)(kh + (size_t)c * LK + kb + k4 * 4);
        }
        __syncthreads();

        float acc[4][4];
        #pragma unroll
        for (int i = 0; i < 4; i++)
            #pragma unroll
            for (int j = 0; j < 4; j++) acc[i][j] = 0.f;

        #pragma unroll 8
        for (int c = 0; c < CH; c++) {
            float4 kv = KVs[c * 32 + lane];            // LDS.128, conflict-free
            #pragma unroll
            for (int i = 0; i < 4; i++) {
                float qv = Qs[c * BQ + warp * 4 + i];  // broadcast
                acc[i][0] += qv * kv.x;
                acc[i][1] += qv * kv.y;
                acc[i][2] += qv * kv.z;
                acc[i][3] += qv * kv.w;
            }
        }

        #pragma unroll
        for (int i = 0; i < 4; i++) {
            const int row = warp * 4 + i;
            const size_t moff = (mrow0 + row) * (size_t)LK + kb + lane * 4;
            bool b0, b1, b2, b3;
            if (mkind == 1) {
                int4 mi = *(const int4*)((const int*)gmask + moff);
                b0 = mi.x != 0; b1 = mi.y != 0; b2 = mi.z != 0; b3 = mi.w != 0;
            } else if (mkind == 2) {
                float4 mf = *(const float4*)((const float*)gmask + moff);
                b0 = mf.x != 0.f; b1 = mf.y != 0.f; b2 = mf.z != 0.f; b3 = mf.w != 0.f;
            } else {
                uchar4 mk = *(const uchar4*)((const unsigned char*)gmask + moff);
                b0 = mk.x != 0; b1 = mk.y != 0; b2 = mk.z != 0; b3 = mk.w != 0;
            }
            float s0 = b0 ? acc[i][0] : -1e30f;
            float s1 = b1 ? acc[i][1] : -1e30f;
            float s2 = b2 ? acc[i][2] : -1e30f;
            float s3 = b3 ? acc[i][3] : -1e30f;
            *(float4*)(wtile + (size_t)row * LK + kb + lane * 4) = make_float4(s0, s1, s2, s3);

            float cm = fmaxf(fmaxf(s0, s1), fmaxf(s2, s3));
            #pragma unroll
            for (int o = 16; o > 0; o >>= 1)
                cm = fmaxf(cm, __shfl_xor_sync(0xffffffffu, cm, o));
            float mn = fmaxf(rm[i], cm);
            float cs = __expf(s0 - mn) + __expf(s1 - mn) + __expf(s2 - mn) + __expf(s3 - mn);
            #pragma unroll
            for (int o = 16; o > 0; o >>= 1)
                cs += __shfl_xor_sync(0xffffffffu, cs, o);
            rs[i] = rs[i] * __expf(rm[i] - mn) + cs;
            rm[i] = mn;
        }
        __syncthreads();   // protect KVs before next chunk load
    }

    if (lane == 0) {
        #pragma unroll
        for (int i = 0; i < 4; i++) {
            rowM[warp * 4 + i] = rm[i];
            rowI[warp * 4 + i] = 1.0f / rs[i];
        }
    }
    __syncthreads();

    // ================= Pass 2: p = exp(S-m)/s -> w;  a += V p^T =================
    float accA[8];
    #pragma unroll
    for (int i = 0; i < 8; i++) accA[i] = 0.f;
    const int qi = lane;
    const int cg = warp;

    for (int cb = 0; cb < NCHK; cb++) {
        const int kb = cb * BK;
        #pragma unroll
        for (int e = tid; e < CH * (BK / 4); e += TPB) {
            int c = e >> 5, k4 = e & 31;
            KVs[c * 32 + k4] = *(const float4*)(vh + (size_t)c * LK + kb + k4 * 4);
        }
        // Normalize raw scores (L2-resident), write final w, stage into Ps.
        #pragma unroll
        for (int j2 = 0; j2 < 4; j2++) {
            int idx = tid + j2 * TPB;
            int qr = idx >> 5, k4 = idx & 31;
            float4 sv = *(const float4*)(wtile + (size_t)qr * LK + kb + k4 * 4);
            float mm = rowM[qr], ii = rowI[qr];
            float4 p;
            p.x = __expf(sv.x - mm) * ii;
            p.y = __expf(sv.y - mm) * ii;
            p.z = __expf(sv.z - mm) * ii;
            p.w = __expf(sv.w - mm) * ii;
            *(float4*)(wtile + (size_t)qr * LK + kb + k4 * 4) = p;
            *(float4*)(Ps + qr * 132 + k4 * 4) = p;
        }
        __syncthreads();

        #pragma unroll 4
        for (int kk = 0; kk < BK; kk += 4) {
            float4 p4 = *(const float4*)(Ps + qi * 132 + kk);
            #pragma unroll
            for (int i = 0; i < 8; i++) {
                float4 vv = KVs[(cg * 8 + i) * 32 + (kk >> 2)];
                accA[i] += p4.x * vv.x + p4.y * vv.y + p4.z * vv.z + p4.w * vv.w;
            }
        }
        __syncthreads();
    }

    #pragma unroll
    for (int i = 0; i < 8; i++) {
        int c = cg * 8 + i;
        ga[((size_t)n * CH + c) * LQ + qbase + qi] = accA[i];
    }
}

extern "C" void kernel_launch(void* const* d_in, const int* in_sizes, int n_in,
                              void* d_out, int out_size)
{
    const float* q = (const float*)d_in[0];
    const float* k = (const float*)d_in[1];
    const float* v = (const float*)d_in[2];
    const void*  mask = d_in[3];
    float* out = (float*)d_out;

    const long long A_ELEMS = (long long)NTOT * CH * LQ;   // 4,194,304
    const long long W_ELEMS = (long long)NTOT * LQ * LK;   // 134,217,728

    float* a_out;
    float* w_out;
    if ((long long)out_size >= A_ELEMS + W_ELEMS) {
        a_out = out;
        w_out = out + A_ELEMS;
    } else if ((long long)out_size >= W_ELEMS) {
        w_out = out;
        cudaGetSymbolAddress((void**)&a_out, g_a_scratch);
    } else {
        a_out = out;
        cudaGetSymbolAddress((void**)&w_out, g_w_scratch);
    }

    cudaFuncSetAttribute(attn_fused_kernel,
                         cudaFuncAttributeMaxDynamicSharedMemorySize, SM_TOT);

    detect_mask_kind_kernel<<<1, 32>>>((const unsigned char*)mask);

    dim3 grid(LQ / BQ, NTOT);
    attn_fused_kernel<<<grid, TPB, SM_TOT>>>(q, k, v, mask, a_out, w_out);
}

// round 4
// speedup vs baseline: 1.0755x; 1.0755x over previous
#include <cuda_runtime.h>
#include <math.h>

#define NTOT 32      // bs * heads
#define CH   64      // head dim
#define LQ   2048
#define LK   2048
#define BQ   64      // q rows per block
#define BK   128     // k cols per chunk
#define NCHK (LK / BK)
#define TPB  256

// Fallback scratch if the harness's d_out does not include the w output.
__device__ float g_w_scratch[(size_t)NTOT * LQ * LK];
__device__ float g_a_scratch[(size_t)NTOT * CH * LQ];

// 0 = uint8/bool, 1 = int32 (0/1), 2 = float32 (0.0/1.0)
__device__ int g_mask_kind;

__global__ void detect_mask_kind_kernel(const unsigned char* __restrict__ m)
{
    if (threadIdx.x != 0 || blockIdx.x != 0) return;
    int nz_r123 = 0, nz_r01 = 0, f32_sig = 0;
    for (int i = 0; i < 4096; i++) {
        unsigned char b = m[i];
        int r = i & 3;
        if (r != 0 && b != 0) nz_r123++;
        if (r <= 1 && b != 0) nz_r01++;
        if (r == 3 && b == 0x3F) f32_sig++;
    }
    int kind;
    if (nz_r123 == 0)                 kind = 1;  // int32 0/1
    else if (nz_r01 == 0 && f32_sig)  kind = 2;  // float32 0.0/1.0
    else                              kind = 0;  // byte bool
    g_mask_kind = kind;
}

// Dynamic shared memory layout (bytes)
#define SM_QS   0                            // float [64][64]   = 16384
#define SM_KV   16384                        // float4 [64][32]  = 32768
#define SM_PS   (16384 + 32768)              // float [64][132]  = 33792
#define SM_RM   (SM_PS + 64 * 132 * 4)       // float [64]
#define SM_RI   (SM_RM + 256)                // float [64]
#define SM_TOT  (SM_RI + 256)                // 83456 total

extern "C" __global__ void __launch_bounds__(TPB, 2)
attn_fused_kernel(const float* __restrict__ gq,
                  const float* __restrict__ gk,
                  const float* __restrict__ gv,
                  const void* __restrict__ gmask,
                  float* __restrict__ ga,
                  float* __restrict__ gw)
{
    extern __shared__ char sm[];
    float*  Qs   = (float*)(sm + SM_QS);    // [c][q]  pre-scaled Q tile (q contiguous)
    float4* KVs  = (float4*)(sm + SM_KV);   // [c][k/4] K or V chunk
    float*  Ps   = (float*)(sm + SM_PS);    // [q][132] normalized probs chunk
    float*  rowM = (float*)(sm + SM_RM);
    float*  rowI = (float*)(sm + SM_RI);

    const int n     = blockIdx.y;           // head index (0..31)
    const int qbase = blockIdx.x * BQ;
    const int tid   = threadIdx.x;
    const int lane  = tid & 31;
    const int warp  = tid >> 5;             // 8 warps
    const int mkind = g_mask_kind;

    const float* qh = gq + (size_t)n * CH * LQ;
    const float* kh = gk + (size_t)n * CH * LK;
    const float* vh = gv + (size_t)n * CH * LK;
    float* wtile = gw + ((size_t)n * LQ + qbase) * LK;
    const size_t mrow0 = (size_t)(n >> 4) * LQ + qbase;   // mask element-row base

    // ---- Load Q tile (pre-scaled by 1/sqrt(ch)); [c][q], q contiguous ----
    #pragma unroll
    for (int e = tid; e < CH * BQ / 4; e += TPB) {
        int c = e >> 4, q4 = e & 15;
        float4 qv = *(const float4*)(qh + (size_t)c * LQ + qbase + q4 * 4);
        qv.x *= 0.125f; qv.y *= 0.125f; qv.z *= 0.125f; qv.w *= 0.125f;
        *(float4*)(Qs + c * BQ + q4 * 4) = qv;
    }
    __syncthreads();

    // ================= Pass 1: S = Q^T K, mask, raw-score write, row stats =================
    // Warp owns q-rows [warp*8, warp*8+8); lane owns k quad lane*4 within chunk.
    float rm[8], rs[8];
    #pragma unroll
    for (int i = 0; i < 8; i++) { rm[i] = -INFINITY; rs[i] = 0.f; }

    for (int cb = 0; cb < NCHK; cb++) {
        const int kb = cb * BK;
        #pragma unroll
        for (int e = tid; e < CH * (BK / 4); e += TPB) {
            int c = e >> 5, k4 = e & 31;
            KVs[c * 32 + k4] = *(const float4*)(kh + (size_t)c * LK + kb + k4 * 4);
        }
        __syncthreads();

        float acc[8][4];
        #pragma unroll
        for (int i = 0; i < 8; i++)
            #pragma unroll
            for (int j = 0; j < 4; j++) acc[i][j] = 0.f;

        #pragma unroll 4
        for (int c = 0; c < CH; c++) {
            float4 kv = KVs[c * 32 + lane];                          // LDS.128, conflict-free
            float4 qa = *(const float4*)(Qs + c * BQ + warp * 8);    // LDS.128 broadcast
            float4 qb = *(const float4*)(Qs + c * BQ + warp * 8 + 4);
            #pragma unroll
            for (int j = 0; j < 4; j++) {
                float kvj = (&kv.x)[j];
                acc[0][j] += qa.x * kvj;
                acc[1][j] += qa.y * kvj;
                acc[2][j] += qa.z * kvj;
                acc[3][j] += qa.w * kvj;
                acc[4][j] += qb.x * kvj;
                acc[5][j] += qb.y * kvj;
                acc[6][j] += qb.z * kvj;
                acc[7][j] += qb.w * kvj;
            }
        }

        #pragma unroll
        for (int i = 0; i < 8; i++) {
            const int row = warp * 8 + i;
            const size_t moff = (mrow0 + row) * (size_t)LK + kb + lane * 4;
            bool b0, b1, b2, b3;
            if (mkind == 1) {
                int4 mi = *(const int4*)((const int*)gmask + moff);
                b0 = mi.x != 0; b1 = mi.y != 0; b2 = mi.z != 0; b3 = mi.w != 0;
            } else if (mkind == 2) {
                float4 mf = *(const float4*)((const float*)gmask + moff);
                b0 = mf.x != 0.f; b1 = mf.y != 0.f; b2 = mf.z != 0.f; b3 = mf.w != 0.f;
            } else {
                uchar4 mk = *(const uchar4*)((const unsigned char*)gmask + moff);
                b0 = mk.x != 0; b1 = mk.y != 0; b2 = mk.z != 0; b3 = mk.w != 0;
            }
            float s0 = b0 ? acc[i][0] : -1e30f;
            float s1 = b1 ? acc[i][1] : -1e30f;
            float s2 = b2 ? acc[i][2] : -1e30f;
            float s3 = b3 ? acc[i][3] : -1e30f;
            *(float4*)(wtile + (size_t)row * LK + kb + lane * 4) = make_float4(s0, s1, s2, s3);

            float cm = fmaxf(fmaxf(s0, s1), fmaxf(s2, s3));
            #pragma unroll
            for (int o = 16; o > 0; o >>= 1)
                cm = fmaxf(cm, __shfl_xor_sync(0xffffffffu, cm, o));
            float mn = fmaxf(rm[i], cm);
            float cs = __expf(s0 - mn) + __expf(s1 - mn) + __expf(s2 - mn) + __expf(s3 - mn);
            #pragma unroll
            for (int o = 16; o > 0; o >>= 1)
                cs += __shfl_xor_sync(0xffffffffu, cs, o);
            rs[i] = rs[i] * __expf(rm[i] - mn) + cs;
            rm[i] = mn;
        }
        __syncthreads();   // protect KVs before next chunk load
    }

    if (lane == 0) {
        #pragma unroll
        for (int i = 0; i < 8; i++) {
            rowM[warp * 8 + i] = rm[i];
            rowI[warp * 8 + i] = 1.0f / rs[i];
        }
    }
    __syncthreads();

    // ================= Pass 2: p = exp(S-m)/s -> w;  a += V p^T =================
    // Thread accumulates a[c, q] for q in {lane, lane+32}, c in [warp*8, warp*8+8).
    float accA[8][2];
    #pragma unroll
    for (int i = 0; i < 8; i++) { accA[i][0] = 0.f; accA[i][1] = 0.f; }

    for (int cb = 0; cb < NCHK; cb++) {
        const int kb = cb * BK;
        #pragma unroll
        for (int e = tid; e < CH * (BK / 4); e += TPB) {
            int c = e >> 5, k4 = e & 31;
            KVs[c * 32 + k4] = *(const float4*)(vh + (size_t)c * LK + kb + k4 * 4);
        }
        // Normalize raw scores (L2-resident), write final w, stage into Ps.
        #pragma unroll
        for (int j2 = 0; j2 < 8; j2++) {
            int idx = tid + j2 * TPB;
            int qr = idx >> 5, k4 = idx & 31;
            float4 sv = *(const float4*)(wtile + (size_t)qr * LK + kb + k4 * 4);
            float mm = rowM[qr], ii = rowI[qr];
            float4 p;
            p.x = __expf(sv.x - mm) * ii;
            p.y = __expf(sv.y - mm) * ii;
            p.z = __expf(sv.z - mm) * ii;
            p.w = __expf(sv.w - mm) * ii;
            *(float4*)(wtile + (size_t)qr * LK + kb + k4 * 4) = p;
            *(float4*)(Ps + qr * 132 + k4 * 4) = p;   // row-contiguous STS, conflict-free
        }
        __syncthreads();

        #pragma unroll 4
        for (int kk4 = 0; kk4 < BK / 4; kk4++) {
            float4 pa = *(const float4*)(Ps + lane * 132 + kk4 * 4);        // conflict-free
            float4 pb = *(const float4*)(Ps + (lane + 32) * 132 + kk4 * 4); // conflict-free
            #pragma unroll
            for (int i = 0; i < 8; i++) {
                float4 vv = KVs[(warp * 8 + i) * 32 + kk4];                 // broadcast
                accA[i][0] += pa.x * vv.x + pa.y * vv.y + pa.z * vv.z + pa.w * vv.w;
                accA[i][1] += pb.x * vv.x + pb.y * vv.y + pb.z * vv.z + pb.w * vv.w;
            }
        }
        __syncthreads();
    }

    #pragma unroll
    for (int i = 0; i < 8; i++) {
        int c = warp * 8 + i;
        float* arow = ga + ((size_t)n * CH + c) * LQ + qbase;
        arow[lane]      = accA[i][0];
        arow[lane + 32] = accA[i][1];
    }
}

extern "C" void kernel_launch(void* const* d_in, const int* in_sizes, int n_in,
                              void* d_out, int out_size)
{
    const float* q = (const float*)d_in[0];
    const float* k = (const float*)d_in[1];
    const float* v = (const float*)d_in[2];
    const void*  mask = d_in[3];
    float* out = (float*)d_out;

    const long long A_ELEMS = (long long)NTOT * CH * LQ;   // 4,194,304
    const long long W_ELEMS = (long long)NTOT * LQ * LK;   // 134,217,728

    float* a_out;
    float* w_out;
    if ((long long)out_size >= A_ELEMS + W_ELEMS) {
        a_out = out;
        w_out = out + A_ELEMS;
    } else if ((long long)out_size >= W_ELEMS) {
        w_out = out;
        cudaGetSymbolAddress((void**)&a_out, g_a_scratch);
    } else {
        a_out = out;
        cudaGetSymbolAddress((void**)&w_out, g_w_scratch);
    }

    cudaFuncSetAttribute(attn_fused_kernel,
                         cudaFuncAttributeMaxDynamicSharedMemorySize, SM_TOT);

    detect_mask_kind_kernel<<<1, 32>>>((const unsigned char*)mask);

    dim3 grid(LQ / BQ, NTOT);
    attn_fused_kernel<<<grid, TPB, SM_TOT>>>(q, k, v, mask, a_out, w_out);
}

// round 9
// speedup vs baseline: 1.4870x; 1.3826x over previous
#include <cuda_runtime.h>
#include <cuda_bf16.h>
#include <math.h>
#include <stdint.h>

#define NTOT 32      // bs * heads
#define CH   64      // head dim
#define LQ   2048
#define LK   2048
#define BQ   128     // q rows per block
#define BK   64      // k cols per chunk
#define NCHK (LK / BK)   // 32
#define TPB  256

// -------- device scratch (no allocations allowed) --------
__device__ float g_w_scratch[(size_t)NTOT * LQ * LK];
__device__ float g_a_scratch[(size_t)NTOT * CH * LQ];
__device__ int   g_mask_kind;   // 0 u8, 1 i32, 2 f32

__global__ void detect_mask_kind_kernel(const unsigned char* __restrict__ m)
{
    if (threadIdx.x != 0 || blockIdx.x != 0) return;
    int nz_r123 = 0, nz_r01 = 0, f32_sig = 0;
    for (int i = 0; i < 4096; i++) {
        unsigned char b = m[i];
        int r = i & 3;
        if (r != 0 && b != 0) nz_r123++;
        if (r <= 1 && b != 0) nz_r01++;
        if (r == 3 && b == 0x3F) f32_sig++;
    }
    int kind;
    if (nz_r123 == 0)                 kind = 1;
    else if (nz_r01 == 0 && f32_sig)  kind = 2;
    else                              kind = 0;
    g_mask_kind = kind;
}

// -------- helpers (plain sm_100 features ONLY: ldmatrix + mma.sync) --------
__device__ __forceinline__ uint32_t sw128(uint32_t off) {
    return off ^ (((off >> 7) & 7) << 4);   // rotate 16B groups across banks per row
}
// tile rows have 128B pitch (64 bf16 cols); r = row, c = bf16 col
__device__ __forceinline__ uint32_t toff(int r, int c) {
    return sw128((uint32_t)(r * 128 + c * 2));
}

__device__ __forceinline__ uint32_t smem_u32(const void* p) {
    uint32_t a;
    asm("{ .reg .u64 t; cvta.to.shared.u64 t, %1; cvt.u32.u64 %0, t; }" : "=r"(a) : "l"(p));
    return a;
}

__device__ __forceinline__ void ldsm4(uint32_t* r, uint32_t addr) {
    asm volatile("ldmatrix.sync.aligned.m8n8.x4.shared.b16 {%0,%1,%2,%3}, [%4];"
        : "=r"(r[0]), "=r"(r[1]), "=r"(r[2]), "=r"(r[3]) : "r"(addr));
}

__device__ __forceinline__ void mma16816(float* d, const uint32_t* a,
                                         uint32_t b0, uint32_t b1) {
    asm volatile("mma.sync.aligned.m16n8k16.row.col.f32.bf16.bf16.f32 "
        "{%0,%1,%2,%3}, {%4,%5,%6,%7}, {%8,%9}, {%0,%1,%2,%3};"
        : "+f"(d[0]), "+f"(d[1]), "+f"(d[2]), "+f"(d[3])
        : "r"(a[0]), "r"(a[1]), "r"(a[2]), "r"(a[3]), "r"(b0), "r"(b1));
}

// split two floats into packed bf16x2 hi and lo parts
__device__ __forceinline__ void split2(float x, float y, uint32_t& hi, uint32_t& lo) {
    __nv_bfloat16 hx = __float2bfloat16(x), hy = __float2bfloat16(y);
    __nv_bfloat16 lx = __float2bfloat16(x - __bfloat162float(hx));
    __nv_bfloat16 ly = __float2bfloat16(y - __bfloat162float(hy));
    hi = (uint32_t)__bfloat16_as_ushort(hx) | ((uint32_t)__bfloat16_as_ushort(hy) << 16);
    lo = (uint32_t)__bfloat16_as_ushort(lx) | ((uint32_t)__bfloat16_as_ushort(ly) << 16);
}
__device__ __forceinline__ void split1(float x, uint16_t& h, uint16_t& l) {
    __nv_bfloat16 hb = __float2bfloat16(x);
    __nv_bfloat16 lb = __float2bfloat16(x - __bfloat162float(hb));
    h = __bfloat16_as_ushort(hb);
    l = __bfloat16_as_ushort(lb);
}

// SMEM layout (bytes)
#define SQH   0        // 16384  Q hi [128][64]bf16 (staging only; reused as SMC)
#define SQL   16384    // 16384  Q lo
#define SKH   32768    //  8192  K/V hi [64][64]bf16
#define SKL   40960    //  8192  K/V lo
#define SMC   0        // 16384  mc[32 chunks][128 rows] f32 (reuses SQH)
#define SRED  49152    //  1024: Mrow[128] @+0, iZrow[128] @+512
#define SMTOT 50176

extern "C" __global__ void __launch_bounds__(TPB, 2)
attn_mma_kernel(const float* __restrict__ gq,
                const float* __restrict__ gk,
                const float* __restrict__ gv,
                const void* __restrict__ gmask,
                float* __restrict__ ga,
                float* __restrict__ gw)
{
    extern __shared__ __align__(1024) char sm[];
    const uint32_t smb = smem_u32(sm);

    const int tid   = threadIdx.x;
    const int warp  = tid >> 5;
    const int lane  = tid & 31;
    const int wrow  = warp * 16;          // this warp's q-row block
    const int n     = blockIdx.y;
    const int qbase = blockIdx.x * BQ;
    const int mkind = g_mask_kind;

    const float* qh_g = gq + (size_t)n * CH * LQ;
    const float* kh_g = gk + (size_t)n * CH * LK;
    const float* vh_g = gv + (size_t)n * CH * LK;
    float* wtile = gw + ((size_t)n * LQ + qbase) * LK;
    const size_t mrow0 = (size_t)(n >> 4) * LQ + qbase;

    // ---- stage Q -> smem bf16 hi/lo, [q][c], pre-scaled by 1/8 ----
    #pragma unroll
    for (int it = 0; it < 8; it++) {
        int e  = tid + it * TPB;          // 0..2047
        int c  = e >> 5;                  // 0..63
        int q0 = (e & 31) * 4;            // 0..124
        float4 qv = *(const float4*)(qh_g + (size_t)c * LQ + qbase + q0);
        float vals[4] = {qv.x * 0.125f, qv.y * 0.125f, qv.z * 0.125f, qv.w * 0.125f};
        #pragma unroll
        for (int j = 0; j < 4; j++) {
            uint16_t hb, lb;
            split1(vals[j], hb, lb);
            uint32_t o = toff(q0 + j, c);
            *(uint16_t*)(sm + SQH + o) = hb;
            *(uint16_t*)(sm + SQL + o) = lb;
        }
    }
    __syncthreads();

    // ---- load Q fragments to registers (A-frag for m16n8k16), then free SQ ----
    uint32_t qfh[4][4], qfl[4][4];        // [kstep][reg]
    {
        int r  = wrow + (lane & 15);
        int cg = (lane >> 4) * 8;
        #pragma unroll
        for (int ks = 0; ks < 4; ks++) {
            ldsm4(qfh[ks], smb + SQH + toff(r, ks * 16 + cg));
            ldsm4(qfl[ks], smb + SQL + toff(r, ks * 16 + cg));
        }
    }
    __syncthreads();   // SQH/SQL now reusable as SMC

    const int qr  = lane >> 2;            // 0..7 (row within warp block; +8 for second)
    const int c2  = (lane & 3) * 2;       // col pair base within 8-wide tile
    float* smc  = (float*)(sm + SMC);
    float* sM   = (float*)(sm + SRED);
    float* siZ  = (float*)(sm + SRED + 512);

    float M0 = -INFINITY, M1 = -INFINITY, Z0 = 0.f, Z1 = 0.f;
    float acc[8][4];
    #pragma unroll
    for (int t = 0; t < 8; t++)
        #pragma unroll
        for (int j = 0; j < 4; j++) acc[t][j] = 0.f;

    for (int cb = 0; cb < NCHK; cb++) {
        const int kb = cb * BK;

        // ---- stage K chunk -> smem [kpos][c] bf16 hi/lo (transpose) ----
        #pragma unroll
        for (int it = 0; it < 4; it++) {
            int e  = tid + it * TPB;      // 0..1023
            int c  = e >> 4;              // 0..63
            int k0 = (e & 15) * 4;        // 0..60
            float4 kv = *(const float4*)(kh_g + (size_t)c * LK + kb + k0);
            float vals[4] = {kv.x, kv.y, kv.z, kv.w};
            #pragma unroll
            for (int j = 0; j < 4; j++) {
                uint16_t hb, lb;
                split1(vals[j], hb, lb);
                uint32_t o = toff(k0 + j, c);
                *(uint16_t*)(sm + SKH + o) = hb;
                *(uint16_t*)(sm + SKL + o) = lb;
            }
        }
        __syncthreads();

        // ---- MMA1: S = Qh*Kh + Qh*Kl + Ql*Kh ----
        float d[8][4];
        #pragma unroll
        for (int t = 0; t < 8; t++)
            #pragma unroll
            for (int j = 0; j < 4; j++) d[t][j] = 0.f;

        {
            int br = ((lane >> 4) & 1) * 8 + (lane & 7);
            int bc = ((lane >> 3) & 1) * 8;
            #pragma unroll
            for (int ks = 0; ks < 4; ks++) {
                #pragma unroll
                for (int tp = 0; tp < 4; tp++) {
                    uint32_t bh[4], bl[4];
                    uint32_t o = toff(tp * 16 + br, ks * 16 + bc);
                    ldsm4(bh, smb + SKH + o);
                    ldsm4(bl, smb + SKL + o);
                    mma16816(d[2*tp],   qfh[ks], bh[0], bh[1]);
                    mma16816(d[2*tp+1], qfh[ks], bh[2], bh[3]);
                    mma16816(d[2*tp],   qfh[ks], bl[0], bl[1]);
                    mma16816(d[2*tp+1], qfh[ks], bl[2], bl[3]);
                    mma16816(d[2*tp],   qfl[ks], bh[0], bh[1]);
                    mma16816(d[2*tp+1], qfl[ks], bh[2], bh[3]);
                }
            }
        }

        // ---- mask ----
        {
            const size_t off0 = (mrow0 + wrow + qr) * (size_t)LK + kb + c2;
            #pragma unroll
            for (int t = 0; t < 8; t++) {
                bool b00, b01, b10, b11;
                if (mkind == 1) {
                    int2 m0 = *(const int2*)((const int*)gmask + off0 + t * 8);
                    int2 m1 = *(const int2*)((const int*)gmask + off0 + t * 8 + 8 * LK);
                    b00 = m0.x != 0; b01 = m0.y != 0; b10 = m1.x != 0; b11 = m1.y != 0;
                } else if (mkind == 2) {
                    float2 m0 = *(const float2*)((const float*)gmask + off0 + t * 8);
                    float2 m1 = *(const float2*)((const float*)gmask + off0 + t * 8 + 8 * LK);
                    b00 = m0.x != 0.f; b01 = m0.y != 0.f; b10 = m1.x != 0.f; b11 = m1.y != 0.f;
                } else {
                    const unsigned char* mb = (const unsigned char*)gmask + off0 + t * 8;
                    b00 = mb[0] != 0; b01 = mb[1] != 0;
                    b10 = mb[8 * LK] != 0; b11 = mb[8 * LK + 1] != 0;
                }
                d[t][0] = b00 ? d[t][0] : -1e30f;
                d[t][1] = b01 ? d[t][1] : -1e30f;
                d[t][2] = b10 ? d[t][2] : -1e30f;
                d[t][3] = b11 ? d[t][3] : -1e30f;
            }
        }

        // ---- chunk max per row (intra-quad shuffles only) ----
        float m0 = -INFINITY, m1 = -INFINITY;
        #pragma unroll
        for (int t = 0; t < 8; t++) {
            m0 = fmaxf(m0, fmaxf(d[t][0], d[t][1]));
            m1 = fmaxf(m1, fmaxf(d[t][2], d[t][3]));
        }
        m0 = fmaxf(m0, __shfl_xor_sync(0xffffffffu, m0, 1));
        m0 = fmaxf(m0, __shfl_xor_sync(0xffffffffu, m0, 2));
        m1 = fmaxf(m1, __shfl_xor_sync(0xffffffffu, m1, 1));
        m1 = fmaxf(m1, __shfl_xor_sync(0xffffffffu, m1, 2));

        const float Mn0 = fmaxf(M0, m0);
        const float Mn1 = fmaxf(M1, m1);
        const float rold0 = __expf(M0 - Mn0);
        const float rold1 = __expf(M1 - Mn1);

        // ---- u = exp(d - Mn) ----
        float s0 = 0.f, s1 = 0.f;
        #pragma unroll
        for (int t = 0; t < 8; t++) {
            d[t][0] = __expf(d[t][0] - Mn0);
            d[t][1] = __expf(d[t][1] - Mn0);
            d[t][2] = __expf(d[t][2] - Mn1);
            d[t][3] = __expf(d[t][3] - Mn1);
            s0 += d[t][0] + d[t][1];
            s1 += d[t][2] + d[t][3];
        }
        s0 += __shfl_xor_sync(0xffffffffu, s0, 1);
        s0 += __shfl_xor_sync(0xffffffffu, s0, 2);
        s1 += __shfl_xor_sync(0xffffffffu, s1, 1);
        s1 += __shfl_xor_sync(0xffffffffu, s1, 2);

        Z0 = Z0 * rold0 + s0;  M0 = Mn0;
        Z1 = Z1 * rold1 + s1;  M1 = Mn1;

        // ---- write unnormalized u to w; record chunk ref max ----
        {
            float* w0 = wtile + (size_t)(wrow + qr) * LK + kb + c2;
            float* w1 = w0 + 8 * LK;
            #pragma unroll
            for (int t = 0; t < 8; t++) {
                *(float2*)(w0 + t * 8) = make_float2(d[t][0], d[t][1]);
                *(float2*)(w1 + t * 8) = make_float2(d[t][2], d[t][3]);
            }
            if ((lane & 3) == 0) {
                smc[cb * 128 + wrow + qr]     = Mn0;
                smc[cb * 128 + wrow + qr + 8] = Mn1;
            }
        }

        __syncthreads();   // all warps done reading K smem

        // ---- stage V chunk -> smem [c][kpos] bf16 hi/lo (direct) ----
        #pragma unroll
        for (int it = 0; it < 4; it++) {
            int e  = tid + it * TPB;
            int c  = e >> 4;              // 0..63
            int k0 = (e & 15) * 4;
            float4 vv = *(const float4*)(vh_g + (size_t)c * LK + kb + k0);
            uint32_t h01, l01, h23, l23;
            split2(vv.x, vv.y, h01, l01);
            split2(vv.z, vv.w, h23, l23);
            uint32_t o = toff(c, k0);     // stays within one 16B swizzle group
            *(uint32_t*)(sm + SKH + o)     = h01;
            *(uint32_t*)(sm + SKH + o + 4) = h23;
            *(uint32_t*)(sm + SKL + o)     = l01;
            *(uint32_t*)(sm + SKL + o + 4) = l23;
        }
        __syncthreads();

        // ---- MMA2: acc = acc*rold + P*V  (P = u, 3-term split) ----
        #pragma unroll
        for (int t = 0; t < 8; t++) {
            acc[t][0] *= rold0; acc[t][1] *= rold0;
            acc[t][2] *= rold1; acc[t][3] *= rold1;
        }
        {
            int br = ((lane >> 4) & 1) * 8 + (lane & 7);
            int bc = ((lane >> 3) & 1) * 8;
            #pragma unroll
            for (int ks = 0; ks < 4; ks++) {
                uint32_t ph[4], pl[4];
                split2(d[2*ks][0],   d[2*ks][1],   ph[0], pl[0]);
                split2(d[2*ks][2],   d[2*ks][3],   ph[1], pl[1]);
                split2(d[2*ks+1][0], d[2*ks+1][1], ph[2], pl[2]);
                split2(d[2*ks+1][2], d[2*ks+1][3], ph[3], pl[3]);
                #pragma unroll
                for (int tp = 0; tp < 4; tp++) {
                    uint32_t bh[4], bl[4];
                    uint32_t o = toff(tp * 16 + br, ks * 16 + bc);
                    ldsm4(bh, smb + SKH + o);
                    ldsm4(bl, smb + SKL + o);
                    mma16816(acc[2*tp],   ph, bh[0], bh[1]);
                    mma16816(acc[2*tp+1], ph, bh[2], bh[3]);
                    mma16816(acc[2*tp],   ph, bl[0], bl[1]);
                    mma16816(acc[2*tp+1], ph, bl[2], bl[3]);
                    mma16816(acc[2*tp],   pl, bh[0], bh[1]);
                    mma16816(acc[2*tp+1], pl, bh[2], bh[3]);
                }
            }
        }
        __syncthreads();   // done with V smem before next chunk's K staging
    }

    // ---- write a = acc / Z  (a[c][q] layout) ----
    const float iZ0 = 1.0f / Z0;
    const float iZ1 = 1.0f / Z1;
    {
        #pragma unroll
        for (int t = 0; t < 8; t++) {
            int c = t * 8 + c2;
            float* a0 = ga + ((size_t)n * CH + c) * LQ + qbase + wrow;
            a0[qr]          = acc[t][0] * iZ0;
            a0[qr + 8]      = acc[t][2] * iZ1;
            float* a1 = a0 + LQ;   // c+1
            a1[qr]          = acc[t][1] * iZ0;
            a1[qr + 8]      = acc[t][3] * iZ1;
        }
        if ((lane & 3) == 0) {
            sM[wrow + qr]      = M0;  siZ[wrow + qr]      = iZ0;
            sM[wrow + qr + 8]  = M1;  siZ[wrow + qr + 8]  = iZ1;
        }
    }
    __syncthreads();

    // ---- fused rescale: w *= exp(mc - M) / Z  (block re-reads its own tile) ----
    for (int i = tid; i < BQ * LK / 4; i += TPB) {
        int row = i >> 9;                  // 512 float4 per row
        int j4  = i & 511;
        int cbk = j4 >> 4;                 // 16 float4 per chunk
        float sc = __expf(smc[cbk * 128 + row] - sM[row]) * siZ[row];
        float4* p = (float4*)(wtile + (size_t)row * LK) + j4;
        float4 u = *p;
        u.x *= sc; u.y *= sc; u.z *= sc; u.w *= sc;
        *p = u;
    }
}

extern "C" void kernel_launch(void* const* d_in, const int* in_sizes, int n_in,
                              void* d_out, int out_size)
{
    const float* q = (const float*)d_in[0];
    const float* k = (const float*)d_in[1];
    const float* v = (const float*)d_in[2];
    const void*  mask = d_in[3];
    float* out = (float*)d_out;

    const long long A_ELEMS = (long long)NTOT * CH * LQ;   // 4,194,304
    const long long W_ELEMS = (long long)NTOT * LQ * LK;   // 134,217,728

    float* a_out;
    float* w_out;
    if ((long long)out_size >= A_ELEMS + W_ELEMS) {
        a_out = out;
        w_out = out + A_ELEMS;
    } else if ((long long)out_size >= W_ELEMS) {
        w_out = out;
        cudaGetSymbolAddress((void**)&a_out, g_a_scratch);
    } else {
        a_out = out;
        cudaGetSymbolAddress((void**)&w_out, g_w_scratch);
    }

    cudaFuncSetAttribute(attn_mma_kernel,
                         cudaFuncAttributeMaxDynamicSharedMemorySize, SMTOT);

    detect_mask_kind_kernel<<<1, 32>>>((const unsigned char*)mask);

    dim3 grid(LQ / BQ, NTOT);
    attn_mma_kernel<<<grid, TPB, SMTOT>>>(q, k, v, mask, a_out, w_out);
}

// round 10
// speedup vs baseline: 1.6391x; 1.1023x over previous
#include <cuda_runtime.h>
#include <cuda_bf16.h>
#include <math.h>
#include <stdint.h>

#define NTOT 32      // bs * heads
#define CH   64      // head dim
#define LQ   2048
#define LK   2048
#define BQ   128     // q rows per block
#define BK   64      // k cols per chunk
#define NCHK (LK / BK)   // 32
#define TPB  256

// -------- device scratch (no allocations allowed) --------
__device__ float g_w_scratch[(size_t)NTOT * LQ * LK];
__device__ float g_a_scratch[(size_t)NTOT * CH * LQ];
__device__ int   g_mask_kind;   // 0 u8, 1 i32, 2 f32

__global__ void detect_mask_kind_kernel(const unsigned char* __restrict__ m)
{
    if (threadIdx.x != 0 || blockIdx.x != 0) return;
    int nz_r123 = 0, nz_r01 = 0, f32_sig = 0;
    for (int i = 0; i < 4096; i++) {
        unsigned char b = m[i];
        int r = i & 3;
        if (r != 0 && b != 0) nz_r123++;
        if (r <= 1 && b != 0) nz_r01++;
        if (r == 3 && b == 0x3F) f32_sig++;
    }
    int kind;
    if (nz_r123 == 0)                 kind = 1;
    else if (nz_r01 == 0 && f32_sig)  kind = 2;
    else                              kind = 0;
    g_mask_kind = kind;
}

// -------- helpers (plain sm_100 features ONLY: ldmatrix + mma.sync) --------
__device__ __forceinline__ uint32_t sw128(uint32_t off) {
    return off ^ (((off >> 7) & 7) << 4);
}
__device__ __forceinline__ uint32_t toff(int r, int c) {   // 128B-pitch rows, bf16 cols
    return sw128((uint32_t)(r * 128 + c * 2));
}

__device__ __forceinline__ uint32_t smem_u32(const void* p) {
    uint32_t a;
    asm("{ .reg .u64 t; cvta.to.shared.u64 t, %1; cvt.u32.u64 %0, t; }" : "=r"(a) : "l"(p));
    return a;
}

__device__ __forceinline__ void ldsm4(uint32_t* r, uint32_t addr) {
    asm volatile("ldmatrix.sync.aligned.m8n8.x4.shared.b16 {%0,%1,%2,%3}, [%4];"
        : "=r"(r[0]), "=r"(r[1]), "=r"(r[2]), "=r"(r[3]) : "r"(addr));
}

__device__ __forceinline__ void mma16816(float* d, const uint32_t* a,
                                         uint32_t b0, uint32_t b1) {
    asm volatile("mma.sync.aligned.m16n8k16.row.col.f32.bf16.bf16.f32 "
        "{%0,%1,%2,%3}, {%4,%5,%6,%7}, {%8,%9}, {%0,%1,%2,%3};"
        : "+f"(d[0]), "+f"(d[1]), "+f"(d[2]), "+f"(d[3])
        : "r"(a[0]), "r"(a[1]), "r"(a[2]), "r"(a[3]), "r"(b0), "r"(b1));
}

__device__ __forceinline__ void split2(float x, float y, uint32_t& hi, uint32_t& lo) {
    __nv_bfloat16 hx = __float2bfloat16(x), hy = __float2bfloat16(y);
    __nv_bfloat16 lx = __float2bfloat16(x - __bfloat162float(hx));
    __nv_bfloat16 ly = __float2bfloat16(y - __bfloat162float(hy));
    hi = (uint32_t)__bfloat16_as_ushort(hx) | ((uint32_t)__bfloat16_as_ushort(hy) << 16);
    lo = (uint32_t)__bfloat16_as_ushort(lx) | ((uint32_t)__bfloat16_as_ushort(ly) << 16);
}
__device__ __forceinline__ void split1(float x, uint16_t& h, uint16_t& l) {
    __nv_bfloat16 hb = __float2bfloat16(x);
    __nv_bfloat16 lb = __float2bfloat16(x - __bfloat162float(hb));
    h = __bfloat16_as_ushort(hb);
    l = __bfloat16_as_ushort(lb);
}

// SMEM layout (bytes)
#define SQH   0        // 16384  Q hi [128][64]bf16  (persistent)
#define SQL   16384    // 16384  Q lo
#define SK0H  32768    //  8192  K buf0 hi [64][64]
#define SK0L  40960    //  8192  K buf0 lo
#define SK1H  49152    //  8192  K buf1 hi
#define SK1L  57344    //  8192  K buf1 lo
#define SVH   65536    //  8192  V hi [64 c][64 k]
#define SVL   73728    //  8192  V lo
#define SMC   81920    // 16384  mc[32 chunks][128 rows] f32
#define SRED  98304    //  1024: Mrow[128] @+0, iZrow[128] @+512
#define SMTOT 99328

extern "C" __global__ void __launch_bounds__(TPB, 2)
attn_mma_kernel(const float* __restrict__ gq,
                const float* __restrict__ gk,
                const float* __restrict__ gv,
                const void* __restrict__ gmask,
                float* __restrict__ ga,
                float* __restrict__ gw)
{
    extern __shared__ __align__(1024) char sm[];
    const uint32_t smb = smem_u32(sm);

    const int tid   = threadIdx.x;
    const int warp  = tid >> 5;
    const int lane  = tid & 31;
    const int wrow  = warp * 16;
    const int n     = blockIdx.y;
    const int qbase = blockIdx.x * BQ;
    const int mkind = g_mask_kind;

    const float* qh_g = gq + (size_t)n * CH * LQ;
    const float* kh_g = gk + (size_t)n * CH * LK;
    const float* vh_g = gv + (size_t)n * CH * LK;
    float* wtile = gw + ((size_t)n * LQ + qbase) * LK;
    const size_t mrow0 = (size_t)(n >> 4) * LQ + qbase;

    // ---- stage Q -> smem bf16 hi/lo, [q][c], pre-scaled by 1/8 (persistent) ----
    #pragma unroll
    for (int it = 0; it < 8; it++) {
        int e  = tid + it * TPB;
        int c  = e >> 5;
        int q0 = (e & 31) * 4;
        float4 qv = *(const float4*)(qh_g + (size_t)c * LQ + qbase + q0);
        float vals[4] = {qv.x * 0.125f, qv.y * 0.125f, qv.z * 0.125f, qv.w * 0.125f};
        #pragma unroll
        for (int j = 0; j < 4; j++) {
            uint16_t hb, lb;
            split1(vals[j], hb, lb);
            uint32_t o = toff(q0 + j, c);
            *(uint16_t*)(sm + SQH + o) = hb;
            *(uint16_t*)(sm + SQL + o) = lb;
        }
    }

    // ---- stage K[0] into K buf0 ----
    #pragma unroll
    for (int it = 0; it < 4; it++) {
        int e  = tid + it * TPB;
        int c  = e >> 4;
        int k0 = (e & 15) * 4;
        float4 kv = *(const float4*)(kh_g + (size_t)c * LK + k0);
        float vals[4] = {kv.x, kv.y, kv.z, kv.w};
        #pragma unroll
        for (int j = 0; j < 4; j++) {
            uint16_t hb, lb;
            split1(vals[j], hb, lb);
            uint32_t o = toff(k0 + j, c);
            *(uint16_t*)(sm + SK0H + o) = hb;
            *(uint16_t*)(sm + SK0L + o) = lb;
        }
    }
    __syncthreads();

    const int qr  = lane >> 2;
    const int c2  = (lane & 3) * 2;
    float* smc  = (float*)(sm + SMC);
    float* sM   = (float*)(sm + SRED);
    float* siZ  = (float*)(sm + SRED + 512);

    float M0 = -INFINITY, M1 = -INFINITY, Z0 = 0.f, Z1 = 0.f;
    float acc[8][4];
    #pragma unroll
    for (int t = 0; t < 8; t++)
        #pragma unroll
        for (int j = 0; j < 4; j++) acc[t][j] = 0.f;

    for (int cb = 0; cb < NCHK; cb++) {
        const int kb = cb * BK;

        // ---- prefetch: V[cb] and K[cb+1] into registers (latency overlaps MMA1) ----
        float4 vpre[4], kpre[4];
        #pragma unroll
        for (int it = 0; it < 4; it++) {
            int e  = tid + it * TPB;
            int c  = e >> 4;
            int k0 = (e & 15) * 4;
            vpre[it] = *(const float4*)(vh_g + (size_t)c * LK + kb + k0);
            if (cb + 1 < NCHK)
                kpre[it] = *(const float4*)(kh_g + (size_t)c * LK + kb + BK + k0);
        }

        // ---- prefetch mask, packed to one bitmask reg ----
        uint32_t mb = 0;
        {
            const size_t off0 = (mrow0 + wrow + qr) * (size_t)LK + kb + c2;
            #pragma unroll
            for (int t = 0; t < 8; t++) {
                bool b00, b01, b10, b11;
                if (mkind == 1) {
                    int2 m0 = *(const int2*)((const int*)gmask + off0 + t * 8);
                    int2 m1 = *(const int2*)((const int*)gmask + off0 + t * 8 + 8 * LK);
                    b00 = m0.x != 0; b01 = m0.y != 0; b10 = m1.x != 0; b11 = m1.y != 0;
                } else if (mkind == 2) {
                    float2 m0 = *(const float2*)((const float*)gmask + off0 + t * 8);
                    float2 m1 = *(const float2*)((const float*)gmask + off0 + t * 8 + 8 * LK);
                    b00 = m0.x != 0.f; b01 = m0.y != 0.f; b10 = m1.x != 0.f; b11 = m1.y != 0.f;
                } else {
                    const unsigned char* mbp = (const unsigned char*)gmask + off0 + t * 8;
                    b00 = mbp[0] != 0; b01 = mbp[1] != 0;
                    b10 = mbp[8 * LK] != 0; b11 = mbp[8 * LK + 1] != 0;
                }
                mb |= ((uint32_t)b00 << (t * 4)) | ((uint32_t)b01 << (t * 4 + 1))
                    | ((uint32_t)b10 << (t * 4 + 2)) | ((uint32_t)b11 << (t * 4 + 3));
            }
        }

        // ---- MMA1: S = Qh*Kh + Qh*Kl + Ql*Kh  (Q re-ldsm'd from smem) ----
        float d[8][4];
        #pragma unroll
        for (int t = 0; t < 8; t++)
            #pragma unroll
            for (int j = 0; j < 4; j++) d[t][j] = 0.f;

        {
            const uint32_t kh_b = smb + ((cb & 1) ? SK1H : SK0H);
            const uint32_t kl_b = smb + ((cb & 1) ? SK1L : SK0L);
            int r  = wrow + (lane & 15);
            int cg = (lane >> 4) * 8;
            int br = ((lane >> 4) & 1) * 8 + (lane & 7);
            int bc = ((lane >> 3) & 1) * 8;
            #pragma unroll
            for (int ks = 0; ks < 4; ks++) {
                uint32_t qfh[4], qfl[4];
                ldsm4(qfh, smb + SQH + toff(r, ks * 16 + cg));
                ldsm4(qfl, smb + SQL + toff(r, ks * 16 + cg));
                #pragma unroll
                for (int tp = 0; tp < 4; tp++) {
                    uint32_t bh[4], bl[4];
                    uint32_t o = toff(tp * 16 + br, ks * 16 + bc);
                    ldsm4(bh, kh_b + o);
                    ldsm4(bl, kl_b + o);
                    mma16816(d[2*tp],   qfh, bh[0], bh[1]);
                    mma16816(d[2*tp+1], qfh, bh[2], bh[3]);
                    mma16816(d[2*tp],   qfh, bl[0], bl[1]);
                    mma16816(d[2*tp+1], qfh, bl[2], bl[3]);
                    mma16816(d[2*tp],   qfl, bh[0], bh[1]);
                    mma16816(d[2*tp+1], qfl, bh[2], bh[3]);
                }
            }
        }

        // ---- apply mask ----
        #pragma unroll
        for (int t = 0; t < 8; t++) {
            d[t][0] = (mb >> (t * 4)     & 1u) ? d[t][0] : -1e30f;
            d[t][1] = (mb >> (t * 4 + 1) & 1u) ? d[t][1] : -1e30f;
            d[t][2] = (mb >> (t * 4 + 2) & 1u) ? d[t][2] : -1e30f;
            d[t][3] = (mb >> (t * 4 + 3) & 1u) ? d[t][3] : -1e30f;
        }

        // ---- chunk max per row (intra-quad shuffles) ----
        float m0 = -INFINITY, m1 = -INFINITY;
        #pragma unroll
        for (int t = 0; t < 8; t++) {
            m0 = fmaxf(m0, fmaxf(d[t][0], d[t][1]));
            m1 = fmaxf(m1, fmaxf(d[t][2], d[t][3]));
        }
        m0 = fmaxf(m0, __shfl_xor_sync(0xffffffffu, m0, 1));
        m0 = fmaxf(m0, __shfl_xor_sync(0xffffffffu, m0, 2));
        m1 = fmaxf(m1, __shfl_xor_sync(0xffffffffu, m1, 1));
        m1 = fmaxf(m1, __shfl_xor_sync(0xffffffffu, m1, 2));

        const float Mn0 = fmaxf(M0, m0);
        const float Mn1 = fmaxf(M1, m1);
        const float rold0 = __expf(M0 - Mn0);
        const float rold1 = __expf(M1 - Mn1);

        // ---- u = exp(d - Mn), row sums ----
        float s0 = 0.f, s1 = 0.f;
        #pragma unroll
        for (int t = 0; t < 8; t++) {
            d[t][0] = __expf(d[t][0] - Mn0);
            d[t][1] = __expf(d[t][1] - Mn0);
            d[t][2] = __expf(d[t][2] - Mn1);
            d[t][3] = __expf(d[t][3] - Mn1);
            s0 += d[t][0] + d[t][1];
            s1 += d[t][2] + d[t][3];
        }
        s0 += __shfl_xor_sync(0xffffffffu, s0, 1);
        s0 += __shfl_xor_sync(0xffffffffu, s0, 2);
        s1 += __shfl_xor_sync(0xffffffffu, s1, 1);
        s1 += __shfl_xor_sync(0xffffffffu, s1, 2);

        Z0 = Z0 * rold0 + s0;  M0 = Mn0;
        Z1 = Z1 * rold1 + s1;  M1 = Mn1;

        // ---- write unnormalized u to w; record chunk max ----
        {
            float* w0 = wtile + (size_t)(wrow + qr) * LK + kb + c2;
            float* w1 = w0 + 8 * LK;
            #pragma unroll
            for (int t = 0; t < 8; t++) {
                *(float2*)(w0 + t * 8) = make_float2(d[t][0], d[t][1]);
                *(float2*)(w1 + t * 8) = make_float2(d[t][2], d[t][3]);
            }
            if ((lane & 3) == 0) {
                smc[cb * 128 + wrow + qr]     = Mn0;
                smc[cb * 128 + wrow + qr + 8] = Mn1;
            }
        }

        // ---- STS prefetched V[cb] -> V buf;  K[cb+1] -> other K buf ----
        #pragma unroll
        for (int it = 0; it < 4; it++) {
            int e  = tid + it * TPB;
            int c  = e >> 4;
            int k0 = (e & 15) * 4;
            uint32_t h01, l01, h23, l23;
            split2(vpre[it].x, vpre[it].y, h01, l01);
            split2(vpre[it].z, vpre[it].w, h23, l23);
            uint32_t o = toff(c, k0);
            *(uint32_t*)(sm + SVH + o)     = h01;
            *(uint32_t*)(sm + SVH + o + 4) = h23;
            *(uint32_t*)(sm + SVL + o)     = l01;
            *(uint32_t*)(sm + SVL + o + 4) = l23;
        }
        if (cb + 1 < NCHK) {
            char* kdh = sm + (((cb + 1) & 1) ? SK1H : SK0H);
            char* kdl = sm + (((cb + 1) & 1) ? SK1L : SK0L);
            #pragma unroll
            for (int it = 0; it < 4; it++) {
                int e  = tid + it * TPB;
                int c  = e >> 4;
                int k0 = (e & 15) * 4;
                float vals[4] = {kpre[it].x, kpre[it].y, kpre[it].z, kpre[it].w};
                #pragma unroll
                for (int j = 0; j < 4; j++) {
                    uint16_t hb, lb;
                    split1(vals[j], hb, lb);
                    uint32_t o = toff(k0 + j, c);
                    *(uint16_t*)(kdh + o) = hb;
                    *(uint16_t*)(kdl + o) = lb;
                }
            }
        }
        __syncthreads();   // V + next-K staged; safe vs all hazards (see timeline)

        // ---- MMA2: acc = acc*rold + P*V  (P = u, 3-term split) ----
        #pragma unroll
        for (int t = 0; t < 8; t++) {
            acc[t][0] *= rold0; acc[t][1] *= rold0;
            acc[t][2] *= rold1; acc[t][3] *= rold1;
        }
        {
            int br = ((lane >> 4) & 1) * 8 + (lane & 7);
            int bc = ((lane >> 3) & 1) * 8;
            #pragma unroll
            for (int ks = 0; ks < 4; ks++) {
                uint32_t ph[4], pl[4];
                split2(d[2*ks][0],   d[2*ks][1],   ph[0], pl[0]);
                split2(d[2*ks][2],   d[2*ks][3],   ph[1], pl[1]);
                split2(d[2*ks+1][0], d[2*ks+1][1], ph[2], pl[2]);
                split2(d[2*ks+1][2], d[2*ks+1][3], ph[3], pl[3]);
                #pragma unroll
                for (int tp = 0; tp < 4; tp++) {
                    uint32_t bh[4], bl[4];
                    uint32_t o = toff(tp * 16 + br, ks * 16 + bc);
                    ldsm4(bh, smb + SVH + o);
                    ldsm4(bl, smb + SVL + o);
                    mma16816(acc[2*tp],   ph, bh[0], bh[1]);
                    mma16816(acc[2*tp+1], ph, bh[2], bh[3]);
                    mma16816(acc[2*tp],   ph, bl[0], bl[1]);
                    mma16816(acc[2*tp+1], ph, bl[2], bl[3]);
                    mma16816(acc[2*tp],   pl, bh[0], bh[1]);
                    mma16816(acc[2*tp+1], pl, bh[2], bh[3]);
                }
            }
        }
        __syncthreads();   // MMA2's V reads done before next iter's V STS
    }

    // ---- write a = acc / Z  (a[c][q] layout) ----
    const float iZ0 = 1.0f / Z0;
    const float iZ1 = 1.0f / Z1;
    {
        #pragma unroll
        for (int t = 0; t < 8; t++) {
            int c = t * 8 + c2;
            float* a0 = ga + ((size_t)n * CH + c) * LQ + qbase + wrow;
            a0[qr]     = acc[t][0] * iZ0;
            a0[qr + 8] = acc[t][2] * iZ1;
            float* a1 = a0 + LQ;
            a1[qr]     = acc[t][1] * iZ0;
            a1[qr + 8] = acc[t][3] * iZ1;
        }
        if ((lane & 3) == 0) {
            sM[wrow + qr]     = M0;  siZ[wrow + qr]     = iZ0;
            sM[wrow + qr + 8] = M1;  siZ[wrow + qr + 8] = iZ1;
        }
    }
    __syncthreads();

    // ---- fused rescale: w *= exp(mc - M) / Z ----
    for (int i = tid; i < BQ * LK / 4; i += TPB) {
        int row = i >> 9;
        int j4  = i & 511;
        int cbk = j4 >> 4;
        float sc = __expf(smc[cbk * 128 + row] - sM[row]) * siZ[row];
        float4* p = (float4*)(wtile + (size_t)row * LK) + j4;
        float4 u = *p;
        u.x *= sc; u.y *= sc; u.z *= sc; u.w *= sc;
        *p = u;
    }
}

extern "C" void kernel_launch(void* const* d_in, const int* in_sizes, int n_in,
                              void* d_out, int out_size)
{
    const float* q = (const float*)d_in[0];
    const float* k = (const float*)d_in[1];
    const float* v = (const float*)d_in[2];
    const void*  mask = d_in[3];
    float* out = (float*)d_out;

    const long long A_ELEMS = (long long)NTOT * CH * LQ;   // 4,194,304
    const long long W_ELEMS = (long long)NTOT * LQ * LK;   // 134,217,728

    float* a_out;
    float* w_out;
    if ((long long)out_size >= A_ELEMS + W_ELEMS) {
        a_out = out;
        w_out = out + A_ELEMS;
    } else if ((long long)out_size >= W_ELEMS) {
        w_out = out;
        cudaGetSymbolAddress((void**)&a_out, g_a_scratch);
    } else {
        a_out = out;
        cudaGetSymbolAddress((void**)&w_out, g_w_scratch);
    }

    cudaFuncSetAttribute(attn_mma_kernel,
                         cudaFuncAttributeMaxDynamicSharedMemorySize, SMTOT);

    detect_mask_kind_kernel<<<1, 32>>>((const unsigned char*)mask);

    dim3 grid(LQ / BQ, NTOT);
    attn_mma_kernel<<<grid, TPB, SMTOT>>>(q, k, v, mask, a_out, w_out);
}

// round 12
// speedup vs baseline: 1.7278x; 1.0541x over previous
#include <cuda_runtime.h>
#include <cuda_fp16.h>
#include <math.h>
#include <stdint.h>

#define NTOT 32      // bs * heads
#define CH   64      // head dim
#define LQ   2048
#define LK   2048
#define BQ   128     // q rows per block
#define BK   64      // k cols per chunk
#define NCHK (LK / BK)   // 32
#define TPB  256

// -------- device scratch (no allocations allowed) --------
__device__ float g_w_scratch[(size_t)NTOT * LQ * LK];
__device__ float g_a_scratch[(size_t)NTOT * CH * LQ];
__device__ int   g_mask_kind;   // 0 u8, 1 i32, 2 f32

__global__ void detect_mask_kind_kernel(const unsigned char* __restrict__ m)
{
    if (threadIdx.x != 0 || blockIdx.x != 0) return;
    int nz_r123 = 0, nz_r01 = 0, f32_sig = 0;
    for (int i = 0; i < 4096; i++) {
        unsigned char b = m[i];
        int r = i & 3;
        if (r != 0 && b != 0) nz_r123++;
        if (r <= 1 && b != 0) nz_r01++;
        if (r == 3 && b == 0x3F) f32_sig++;
    }
    int kind;
    if (nz_r123 == 0)                 kind = 1;
    else if (nz_r01 == 0 && f32_sig)  kind = 2;
    else                              kind = 0;
    g_mask_kind = kind;
}

// -------- helpers (plain sm_100 features ONLY: ldmatrix + mma.sync) --------
__device__ __forceinline__ uint32_t sw128(uint32_t off) {
    return off ^ (((off >> 7) & 7) << 4);
}
__device__ __forceinline__ uint32_t toff(int r, int c) {   // 128B-pitch rows, fp16 cols
    return sw128((uint32_t)(r * 128 + c * 2));
}

__device__ __forceinline__ uint32_t smem_u32(const void* p) {
    uint32_t a;
    asm("{ .reg .u64 t; cvta.to.shared.u64 t, %1; cvt.u32.u64 %0, t; }" : "=r"(a) : "l"(p));
    return a;
}

__device__ __forceinline__ void ldsm4(uint32_t* r, uint32_t addr) {
    asm volatile("ldmatrix.sync.aligned.m8n8.x4.shared.b16 {%0,%1,%2,%3}, [%4];"
        : "=r"(r[0]), "=r"(r[1]), "=r"(r[2]), "=r"(r[3]) : "r"(addr));
}

__device__ __forceinline__ void mma16816(float* d, const uint32_t* a,
                                         uint32_t b0, uint32_t b1) {
    asm volatile("mma.sync.aligned.m16n8k16.row.col.f32.f16.f16.f32 "
        "{%0,%1,%2,%3}, {%4,%5,%6,%7}, {%8,%9}, {%0,%1,%2,%3};"
        : "+f"(d[0]), "+f"(d[1]), "+f"(d[2]), "+f"(d[3])
        : "r"(a[0]), "r"(a[1]), "r"(a[2]), "r"(a[3]), "r"(b0), "r"(b1));
}

// fp16 hi/lo split of one float
__device__ __forceinline__ void split1h(float x, uint16_t& h, uint16_t& l) {
    __half hb = __float2half_rn(x);
    __half lb = __float2half_rn(x - __half2float(hb));
    h = __half_as_ushort(hb);
    l = __half_as_ushort(lb);
}
// pack two floats to fp16x2 (hi only)
__device__ __forceinline__ uint32_t pack2h(float x, float y) {
    __half2 h = __float22half2_rn(make_float2(x, y));
    return *(uint32_t*)&h;
}
// pack two floats to fp16x2 hi and lo parts
__device__ __forceinline__ void split2h(float x, float y, uint32_t& hi, uint32_t& lo) {
    __half hx = __float2half_rn(x), hy = __float2half_rn(y);
    __half lx = __float2half_rn(x - __half2float(hx));
    __half ly = __float2half_rn(y - __half2float(hy));
    hi = (uint32_t)__half_as_ushort(hx) | ((uint32_t)__half_as_ushort(hy) << 16);
    lo = (uint32_t)__half_as_ushort(lx) | ((uint32_t)__half_as_ushort(ly) << 16);
}

// SMEM layout (bytes)
#define SQH   0        // 16384  Q hi [128][64] fp16 (persistent)
#define SK0H  16384    //  8192  K buf0 hi [64 k][64 c]
#define SK0L  24576    //  8192  K buf0 lo
#define SK1H  32768    //  8192  K buf1 hi
#define SK1L  40960    //  8192  K buf1 lo
#define SVH0  49152    //  8192  V buf0 hi [64 c][64 k]
#define SVL0  57344    //  8192  V buf0 lo
#define SVH1  65536    //  8192  V buf1 hi
#define SVL1  73728    //  8192  V buf1 lo
#define SMC   81920    // 16384  mc[32 chunks][128 rows] f32
#define SRED  98304    //  1024: Mrow[128] @+0, iZrow[128] @+512
#define SMTOT 99328

extern "C" __global__ void __launch_bounds__(TPB, 2)
attn_mma_kernel(const float* __restrict__ gq,
                const float* __restrict__ gk,
                const float* __restrict__ gv,
                const void* __restrict__ gmask,
                float* __restrict__ ga,
                float* __restrict__ gw)
{
    extern __shared__ __align__(1024) char sm[];
    const uint32_t smb = smem_u32(sm);

    const int tid   = threadIdx.x;
    const int warp  = tid >> 5;
    const int lane  = tid & 31;
    const int wrow  = warp * 16;
    const int n     = blockIdx.y;
    const int qbase = blockIdx.x * BQ;
    const int mkind = g_mask_kind;

    const float* qh_g = gq + (size_t)n * CH * LQ;
    const float* kh_g = gk + (size_t)n * CH * LK;
    const float* vh_g = gv + (size_t)n * CH * LK;
    float* wtile = gw + ((size_t)n * LQ + qbase) * LK;
    const size_t mrow0 = (size_t)(n >> 4) * LQ + qbase;

    // ---- stage Q -> smem fp16 HI only, [q][c], pre-scaled by 1/8 ----
    #pragma unroll
    for (int it = 0; it < 8; it++) {
        int e  = tid + it * TPB;
        int c  = e >> 5;
        int q0 = (e & 31) * 4;
        float4 qv = *(const float4*)(qh_g + (size_t)c * LQ + qbase + q0);
        *(uint16_t*)(sm + SQH + toff(q0 + 0, c)) = __half_as_ushort(__float2half_rn(qv.x * 0.125f));
        *(uint16_t*)(sm + SQH + toff(q0 + 1, c)) = __half_as_ushort(__float2half_rn(qv.y * 0.125f));
        *(uint16_t*)(sm + SQH + toff(q0 + 2, c)) = __half_as_ushort(__float2half_rn(qv.z * 0.125f));
        *(uint16_t*)(sm + SQH + toff(q0 + 3, c)) = __half_as_ushort(__float2half_rn(qv.w * 0.125f));
    }

    // ---- stage K[0] hi/lo -> Kbuf0 ; V[0] hi/lo -> Vbuf0 ----
    #pragma unroll
    for (int it = 0; it < 4; it++) {
        int e  = tid + it * TPB;
        int c  = e >> 4;
        int k0 = (e & 15) * 4;
        float4 kv = *(const float4*)(kh_g + (size_t)c * LK + k0);
        float kvals[4] = {kv.x, kv.y, kv.z, kv.w};
        #pragma unroll
        for (int j = 0; j < 4; j++) {
            uint16_t hb, lb;
            split1h(kvals[j], hb, lb);
            uint32_t o = toff(k0 + j, c);
            *(uint16_t*)(sm + SK0H + o) = hb;
            *(uint16_t*)(sm + SK0L + o) = lb;
        }
        float4 vv = *(const float4*)(vh_g + (size_t)c * LK + k0);
        uint32_t h01, l01, h23, l23;
        split2h(vv.x, vv.y, h01, l01);
        split2h(vv.z, vv.w, h23, l23);
        uint32_t o = toff(c, k0);
        *(uint32_t*)(sm + SVH0 + o)     = h01;
        *(uint32_t*)(sm + SVH0 + o + 4) = h23;
        *(uint32_t*)(sm + SVL0 + o)     = l01;
        *(uint32_t*)(sm + SVL0 + o + 4) = l23;
    }
    __syncthreads();

    const int qr  = lane >> 2;
    const int c2  = (lane & 3) * 2;
    float* smc  = (float*)(sm + SMC);
    float* sM   = (float*)(sm + SRED);
    float* siZ  = (float*)(sm + SRED + 512);

    float M0 = -INFINITY, M1 = -INFINITY, Z0 = 0.f, Z1 = 0.f;
    float acc[8][4];
    #pragma unroll
    for (int t = 0; t < 8; t++)
        #pragma unroll
        for (int j = 0; j < 4; j++) acc[t][j] = 0.f;

    for (int cb = 0; cb < NCHK; cb++) {
        const int kb = cb * BK;

        // ---- prefetch K[cb+1], V[cb+1] into regs (latency hides under MMA1) ----
        float4 kpre[4], vpre[4];
        if (cb + 1 < NCHK) {
            #pragma unroll
            for (int it = 0; it < 4; it++) {
                int e  = tid + it * TPB;
                int c  = e >> 4;
                int k0 = (e & 15) * 4;
                kpre[it] = *(const float4*)(kh_g + (size_t)c * LK + kb + BK + k0);
                vpre[it] = *(const float4*)(vh_g + (size_t)c * LK + kb + BK + k0);
            }
        }

        // ---- prefetch mask -> bitmask reg ----
        uint32_t mb = 0;
        {
            const size_t off0 = (mrow0 + wrow + qr) * (size_t)LK + kb + c2;
            #pragma unroll
            for (int t = 0; t < 8; t++) {
                bool b00, b01, b10, b11;
                if (mkind == 1) {
                    int2 m0 = *(const int2*)((const int*)gmask + off0 + t * 8);
                    int2 m1 = *(const int2*)((const int*)gmask + off0 + t * 8 + 8 * LK);
                    b00 = m0.x != 0; b01 = m0.y != 0; b10 = m1.x != 0; b11 = m1.y != 0;
                } else if (mkind == 2) {
                    float2 m0 = *(const float2*)((const float*)gmask + off0 + t * 8);
                    float2 m1 = *(const float2*)((const float*)gmask + off0 + t * 8 + 8 * LK);
                    b00 = m0.x != 0.f; b01 = m0.y != 0.f; b10 = m1.x != 0.f; b11 = m1.y != 0.f;
                } else {
                    const unsigned char* mbp = (const unsigned char*)gmask + off0 + t * 8;
                    b00 = mbp[0] != 0; b01 = mbp[1] != 0;
                    b10 = mbp[8 * LK] != 0; b11 = mbp[8 * LK + 1] != 0;
                }
                mb |= ((uint32_t)b00 << (t * 4)) | ((uint32_t)b01 << (t * 4 + 1))
                    | ((uint32_t)b10 << (t * 4 + 2)) | ((uint32_t)b11 << (t * 4 + 3));
            }
        }

        // ---- MMA1: S = Qh*(Kh + Kl)  (fp16 2-term) ----
        float d[8][4];
        #pragma unroll
        for (int t = 0; t < 8; t++)
            #pragma unroll
            for (int j = 0; j < 4; j++) d[t][j] = 0.f;

        {
            const uint32_t kh_b = smb + ((cb & 1) ? SK1H : SK0H);
            const uint32_t kl_b = smb + ((cb & 1) ? SK1L : SK0L);
            int r  = wrow + (lane & 15);
            int cg = (lane >> 4) * 8;
            int br = ((lane >> 4) & 1) * 8 + (lane & 7);
            int bc = ((lane >> 3) & 1) * 8;
            #pragma unroll
            for (int ks = 0; ks < 4; ks++) {
                uint32_t qf[4];
                ldsm4(qf, smb + SQH + toff(r, ks * 16 + cg));
                #pragma unroll
                for (int tp = 0; tp < 4; tp++) {
                    uint32_t bh[4], bl[4];
                    uint32_t o = toff(tp * 16 + br, ks * 16 + bc);
                    ldsm4(bh, kh_b + o);
                    ldsm4(bl, kl_b + o);
                    mma16816(d[2*tp],   qf, bh[0], bh[1]);
                    mma16816(d[2*tp+1], qf, bh[2], bh[3]);
                    mma16816(d[2*tp],   qf, bl[0], bl[1]);
                    mma16816(d[2*tp+1], qf, bl[2], bl[3]);
                }
            }
        }

        // ---- mask ----
        #pragma unroll
        for (int t = 0; t < 8; t++) {
            d[t][0] = (mb >> (t * 4)     & 1u) ? d[t][0] : -1e30f;
            d[t][1] = (mb >> (t * 4 + 1) & 1u) ? d[t][1] : -1e30f;
            d[t][2] = (mb >> (t * 4 + 2) & 1u) ? d[t][2] : -1e30f;
            d[t][3] = (mb >> (t * 4 + 3) & 1u) ? d[t][3] : -1e30f;
        }

        // ---- chunk max per row ----
        float m0 = -INFINITY, m1 = -INFINITY;
        #pragma unroll
        for (int t = 0; t < 8; t++) {
            m0 = fmaxf(m0, fmaxf(d[t][0], d[t][1]));
            m1 = fmaxf(m1, fmaxf(d[t][2], d[t][3]));
        }
        m0 = fmaxf(m0, __shfl_xor_sync(0xffffffffu, m0, 1));
        m0 = fmaxf(m0, __shfl_xor_sync(0xffffffffu, m0, 2));
        m1 = fmaxf(m1, __shfl_xor_sync(0xffffffffu, m1, 1));
        m1 = fmaxf(m1, __shfl_xor_sync(0xffffffffu, m1, 2));

        const float Mn0 = fmaxf(M0, m0);
        const float Mn1 = fmaxf(M1, m1);
        const float rold0 = __expf(M0 - Mn0);
        const float rold1 = __expf(M1 - Mn1);

        // ---- u = exp(d - Mn), row sums ----
        float s0 = 0.f, s1 = 0.f;
        #pragma unroll
        for (int t = 0; t < 8; t++) {
            d[t][0] = __expf(d[t][0] - Mn0);
            d[t][1] = __expf(d[t][1] - Mn0);
            d[t][2] = __expf(d[t][2] - Mn1);
            d[t][3] = __expf(d[t][3] - Mn1);
            s0 += d[t][0] + d[t][1];
            s1 += d[t][2] + d[t][3];
        }
        s0 += __shfl_xor_sync(0xffffffffu, s0, 1);
        s0 += __shfl_xor_sync(0xffffffffu, s0, 2);
        s1 += __shfl_xor_sync(0xffffffffu, s1, 1);
        s1 += __shfl_xor_sync(0xffffffffu, s1, 2);

        Z0 = Z0 * rold0 + s0;  M0 = Mn0;
        Z1 = Z1 * rold1 + s1;  M1 = Mn1;

        // ---- write unnormalized u to w; record chunk max ----
        {
            float* w0 = wtile + (size_t)(wrow + qr) * LK + kb + c2;
            float* w1 = w0 + 8 * LK;
            #pragma unroll
            for (int t = 0; t < 8; t++) {
                *(float2*)(w0 + t * 8) = make_float2(d[t][0], d[t][1]);
                *(float2*)(w1 + t * 8) = make_float2(d[t][2], d[t][3]);
            }
            if ((lane & 3) == 0) {
                smc[cb * 128 + wrow + qr]     = Mn0;
                smc[cb * 128 + wrow + qr + 8] = Mn1;
            }
        }

        // ---- STS K[cb+1], V[cb+1] -> other buffers (safe: their last readers
        //      finished before the end-of-iteration sync of iter cb-1) ----
        if (cb + 1 < NCHK) {
            char* kdh = sm + (((cb + 1) & 1) ? SK1H : SK0H);
            char* kdl = sm + (((cb + 1) & 1) ? SK1L : SK0L);
            char* vdh = sm + (((cb + 1) & 1) ? SVH1 : SVH0);
            char* vdl = sm + (((cb + 1) & 1) ? SVL1 : SVL0);
            #pragma unroll
            for (int it = 0; it < 4; it++) {
                int e  = tid + it * TPB;
                int c  = e >> 4;
                int k0 = (e & 15) * 4;
                float kvals[4] = {kpre[it].x, kpre[it].y, kpre[it].z, kpre[it].w};
                #pragma unroll
                for (int j = 0; j < 4; j++) {
                    uint16_t hb, lb;
                    split1h(kvals[j], hb, lb);
                    uint32_t o = toff(k0 + j, c);
                    *(uint16_t*)(kdh + o) = hb;
                    *(uint16_t*)(kdl + o) = lb;
                }
                uint32_t h01, l01, h23, l23;
                split2h(vpre[it].x, vpre[it].y, h01, l01);
                split2h(vpre[it].z, vpre[it].w, h23, l23);
                uint32_t o = toff(c, k0);
                *(uint32_t*)(vdh + o)     = h01;
                *(uint32_t*)(vdh + o + 4) = h23;
                *(uint32_t*)(vdl + o)     = l01;
                *(uint32_t*)(vdl + o + 4) = l23;
            }
        }

        // ---- MMA2: acc = acc*rold + Ph*(Vh + Vl)  (current V buffer) ----
        #pragma unroll
        for (int t = 0; t < 8; t++) {
            acc[t][0] *= rold0; acc[t][1] *= rold0;
            acc[t][2] *= rold1; acc[t][3] *= rold1;
        }
        {
            const uint32_t vh_b = smb + ((cb & 1) ? SVH1 : SVH0);
            const uint32_t vl_b = smb + ((cb & 1) ? SVL1 : SVL0);
            int br = ((lane >> 4) & 1) * 8 + (lane & 7);
            int bc = ((lane >> 3) & 1) * 8;
            #pragma unroll
            for (int ks = 0; ks < 4; ks++) {
                uint32_t ph[4];
                ph[0] = pack2h(d[2*ks][0],   d[2*ks][1]);
                ph[1] = pack2h(d[2*ks][2],   d[2*ks][3]);
                ph[2] = pack2h(d[2*ks+1][0], d[2*ks+1][1]);
                ph[3] = pack2h(d[2*ks+1][2], d[2*ks+1][3]);
                #pragma unroll
                for (int tp = 0; tp < 4; tp++) {
                    uint32_t vh[4], vl[4];
                    uint32_t o = toff(tp * 16 + br, ks * 16 + bc);
                    ldsm4(vh, vh_b + o);
                    ldsm4(vl, vl_b + o);
                    mma16816(acc[2*tp],   ph, vh[0], vh[1]);
                    mma16816(acc[2*tp+1], ph, vh[2], vh[3]);
                    mma16816(acc[2*tp],   ph, vl[0], vl[1]);
                    mma16816(acc[2*tp+1], ph, vl[2], vl[3]);
                }
            }
        }

        __syncthreads();   // single barrier per chunk: separates this iter's
                           // buffer reads from next iter's STS overwrites
    }

    // ---- write a = acc / Z  (a[c][q] layout) ----
    const float iZ0 = 1.0f / Z0;
    const float iZ1 = 1.0f / Z1;
    {
        #pragma unroll
        for (int t = 0; t < 8; t++) {
            int c = t * 8 + c2;
            float* a0 = ga + ((size_t)n * CH + c) * LQ + qbase + wrow;
            a0[qr]     = acc[t][0] * iZ0;
            a0[qr + 8] = acc[t][2] * iZ1;
            float* a1 = a0 + LQ;
            a1[qr]     = acc[t][1] * iZ0;
            a1[qr + 8] = acc[t][3] * iZ1;
        }
        if ((lane & 3) == 0) {
            sM[wrow + qr]     = M0;  siZ[wrow + qr]     = iZ0;
            sM[wrow + qr + 8] = M1;  siZ[wrow + qr + 8] = iZ1;
        }
    }
    __syncthreads();

    // ---- fused rescale: w *= exp(mc - M) / Z ----
    for (int i = tid; i < BQ * LK / 4; i += TPB) {
        int row = i >> 9;
        int j4  = i & 511;
        int cbk = j4 >> 4;
        float sc = __expf(smc[cbk * 128 + row] - sM[row]) * siZ[row];
        float4* p = (float4*)(wtile + (size_t)row * LK) + j4;
        float4 u = *p;
        u.x *= sc; u.y *= sc; u.z *= sc; u.w *= sc;
        *p = u;
    }
}

extern "C" void kernel_launch(void* const* d_in, const int* in_sizes, int n_in,
                              void* d_out, int out_size)
{
    const float* q = (const float*)d_in[0];
    const float* k = (const float*)d_in[1];
    const float* v = (const float*)d_in[2];
    const void*  mask = d_in[3];
    float* out = (float*)d_out;

    const long long A_ELEMS = (long long)NTOT * CH * LQ;   // 4,194,304
    const long long W_ELEMS = (long long)NTOT * LQ * LK;   // 134,217,728

    float* a_out;
    float* w_out;
    if ((long long)out_size >= A_ELEMS + W_ELEMS) {
        a_out = out;
        w_out = out + A_ELEMS;
    } else if ((long long)out_size >= W_ELEMS) {
        w_out = out;
        cudaGetSymbolAddress((void**)&a_out, g_a_scratch);
    } else {
        a_out = out;
        cudaGetSymbolAddress((void**)&w_out, g_w_scratch);
    }

    cudaFuncSetAttribute(attn_mma_kernel,
                         cudaFuncAttributeMaxDynamicSharedMemorySize, SMTOT);

    detect_mask_kind_kernel<<<1, 32>>>((const unsigned char*)mask);

    dim3 grid(LQ / BQ, NTOT);
    attn_mma_kernel<<<grid, TPB, SMTOT>>>(q, k, v, mask, a_out, w_out);
}

// round 13
// speedup vs baseline: 2.1177x; 1.2257x over previous
#include <cuda_runtime.h>
#include <cuda_fp16.h>
#include <math.h>
#include <stdint.h>

#define NTOT 32      // bs * heads
#define CH   64      // head dim
#define LQ   2048
#define LK   2048
#define BQ   128     // q rows per block
#define BK   64      // k cols per chunk
#define NCHK (LK / BK)   // 32
#define TPB  256

// -------- device scratch (no allocations allowed) --------
__device__ float  g_w_scratch[(size_t)NTOT * LQ * LK];
__device__ float  g_a_scratch[(size_t)NTOT * CH * LQ];
__device__ __half g_q16 [(size_t)NTOT * LQ * CH];   // [n][q][c], hi, pre-scaled
__device__ __half g_k16h[(size_t)NTOT * LK * CH];   // [n][k][c]
__device__ __half g_k16l[(size_t)NTOT * LK * CH];
__device__ __half g_v16h[(size_t)NTOT * CH * LK];   // [n][c][k]
__device__ __half g_v16l[(size_t)NTOT * CH * LK];
__device__ int    g_mask_kind;   // 0 u8, 1 i32, 2 f32

__global__ void detect_mask_kind_kernel(const unsigned char* __restrict__ m)
{
    if (threadIdx.x != 0 || blockIdx.x != 0) return;
    int nz_r123 = 0, nz_r01 = 0, f32_sig = 0;
    for (int i = 0; i < 4096; i++) {
        unsigned char b = m[i];
        int r = i & 3;
        if (r != 0 && b != 0) nz_r123++;
        if (r <= 1 && b != 0) nz_r01++;
        if (r == 3 && b == 0x3F) f32_sig++;
    }
    int kind;
    if (nz_r123 == 0)                 kind = 1;
    else if (nz_r01 == 0 && f32_sig)  kind = 2;
    else                              kind = 0;
    g_mask_kind = kind;
}

// ---- one-time convert: fp32 -> fp16 hi/lo with layout transform ----
// which(blockIdx.z): 0 = Q (transpose [c][q]->[q][c], *0.125, hi only)
//                    1 = K (transpose [c][k]->[k][c], hi+lo)
//                    2 = V (stream [c][k], hi+lo)
__global__ void __launch_bounds__(256)
convert_kernel(const float* __restrict__ gq,
               const float* __restrict__ gk,
               const float* __restrict__ gv)
{
    __shared__ float ts[64][65];
    const int tid  = threadIdx.x;
    const int tile = blockIdx.x;   // 0..31 (64-wide slice of q/k)
    const int n    = blockIdx.y;
    const int which = blockIdx.z;
    const size_t hb = (size_t)n * CH * LK;

    if (which == 2) {
        #pragma unroll
        for (int it = 0; it < 16; it++) {
            int flat = tile * 4096 + tid + it * 256;
            float v = gv[hb + flat];
            __half hv = __float2half_rn(v);
            g_v16h[hb + flat] = hv;
            g_v16l[hb + flat] = __float2half_rn(v - __half2float(hv));
        }
        return;
    }
    const float* src = (which == 0) ? gq : gk;
    #pragma unroll
    for (int it = 0; it < 16; it++) {
        int flat = tid + it * 256;
        int c = flat >> 6, x = flat & 63;
        ts[c][x] = src[hb + (size_t)c * LK + tile * 64 + x];
    }
    __syncthreads();
    #pragma unroll
    for (int it = 0; it < 16; it++) {
        int flat = tid + it * 256;
        int x = flat >> 6, c = flat & 63;
        float v = ts[c][x];
        size_t dst = hb + (size_t)(tile * 64 + x) * 64 + c;
        if (which == 0) {
            g_q16[dst] = __float2half_rn(v * 0.125f);
        } else {
            __half hv = __float2half_rn(v);
            g_k16h[dst] = hv;
            g_k16l[dst] = __float2half_rn(v - __half2float(hv));
        }
    }
}

// -------- helpers --------
__device__ __forceinline__ uint32_t sw128(uint32_t off) {
    return off ^ (((off >> 7) & 7) << 4);
}
__device__ __forceinline__ uint32_t toff(int r, int c) {   // 128B-pitch rows, fp16 cols
    return sw128((uint32_t)(r * 128 + c * 2));
}
__device__ __forceinline__ uint32_t smem_u32(const void* p) {
    uint32_t a;
    asm("{ .reg .u64 t; cvta.to.shared.u64 t, %1; cvt.u32.u64 %0, t; }" : "=r"(a) : "l"(p));
    return a;
}
__device__ __forceinline__ void ldsm4(uint32_t* r, uint32_t addr) {
    asm volatile("ldmatrix.sync.aligned.m8n8.x4.shared.b16 {%0,%1,%2,%3}, [%4];"
        : "=r"(r[0]), "=r"(r[1]), "=r"(r[2]), "=r"(r[3]) : "r"(addr));
}
__device__ __forceinline__ void mma16816(float* d, const uint32_t* a,
                                         uint32_t b0, uint32_t b1) {
    asm volatile("mma.sync.aligned.m16n8k16.row.col.f32.f16.f16.f32 "
        "{%0,%1,%2,%3}, {%4,%5,%6,%7}, {%8,%9}, {%0,%1,%2,%3};"
        : "+f"(d[0]), "+f"(d[1]), "+f"(d[2]), "+f"(d[3])
        : "r"(a[0]), "r"(a[1]), "r"(a[2]), "r"(a[3]), "r"(b0), "r"(b1));
}
__device__ __forceinline__ uint32_t pack2h(float x, float y) {
    __half2 h = __float22half2_rn(make_float2(x, y));
    return *(uint32_t*)&h;
}
__device__ __forceinline__ void cpa16(uint32_t dst, const void* src) {
    asm volatile("cp.async.cg.shared.global [%0], [%1], 16;" :: "r"(dst), "l"(src));
}
#define CP_COMMIT() asm volatile("cp.async.commit_group;" ::: "memory")
#define CP_WAIT0()  asm volatile("cp.async.wait_group 0;" ::: "memory")

// SMEM layout (bytes)
#define SK0H  0        //  8192  K buf0 hi [64 k][64 c]   (Q staged here pre-loop)
#define SK0L  8192     //  8192  K buf0 lo
#define SK1H  16384    //  8192  K buf1 hi
#define SK1L  24576    //  8192  K buf1 lo
#define SVH0  32768    //  8192  V buf0 hi [64 c][64 k]
#define SVL0  40960    //  8192  V buf0 lo
#define SVH1  49152    //  8192  V buf1 hi
#define SVL1  57344    //  8192  V buf1 lo
#define SMC   65536    // 16384  mc[32 chunks][128 rows] f32
#define SRED  81920    //  1024: Mrow[128] @+0, iZrow[128] @+512
#define SMTOT 82944

extern "C" __global__ void __launch_bounds__(TPB, 2)
attn_mma_kernel(const __half* __restrict__ q16,
                const __half* __restrict__ k16h,
                const __half* __restrict__ k16l,
                const __half* __restrict__ v16h,
                const __half* __restrict__ v16l,
                const void* __restrict__ gmask,
                float* __restrict__ ga,
                float* __restrict__ gw)
{
    extern __shared__ __align__(1024) char sm[];
    const uint32_t smb = smem_u32(sm);

    const int tid   = threadIdx.x;
    const int warp  = tid >> 5;
    const int lane  = tid & 31;
    const int wrow  = warp * 16;
    const int n     = blockIdx.y;
    const int qbase = blockIdx.x * BQ;
    const int mkind = g_mask_kind;

    const __half* qh_g = q16 + ((size_t)n * LQ + qbase) * CH;     // [128][64]
    const __half* khh  = k16h + (size_t)n * LK * CH;              // [k][64]
    const __half* khl  = k16l + (size_t)n * LK * CH;
    const __half* vhh  = v16h + (size_t)n * CH * LK;              // [64][k]
    const __half* vhl  = v16l + (size_t)n * CH * LK;
    float* wtile = gw + ((size_t)n * LQ + qbase) * LK;
    const size_t mrow0 = (size_t)(n >> 4) * LQ + qbase;

    // ---- stage Q via cp.async into K buf0 region (16KB), load frags, free it ----
    #pragma unroll
    for (int it = 0; it < 4; it++) {
        int idx = tid + it * TPB;         // 0..1023
        int r = idx >> 3, g = idx & 7;
        cpa16(smb + SK0H + toff(r, g * 8), qh_g + (size_t)r * CH + g * 8);
    }
    CP_COMMIT();
    CP_WAIT0();
    __syncthreads();

    uint32_t qf[4][4];                    // Q hi fragments, persistent in regs
    {
        int r  = wrow + (lane & 15);
        int cg = (lane >> 4) * 8;
        #pragma unroll
        for (int ks = 0; ks < 4; ks++)
            ldsm4(qf[ks], smb + SK0H + toff(r, ks * 16 + cg));
    }
    __syncthreads();   // Q staging area about to be overwritten by chunk 0

    // ---- submit chunk 0 into buffers 0 ----
    #pragma unroll
    for (int it = 0; it < 2; it++) {
        int idx = tid + it * TPB;         // 0..511
        int r = idx >> 3, g = idx & 7;
        uint32_t o = toff(r, g * 8);
        cpa16(smb + SK0H + o, khh + (size_t)r * CH + g * 8);
        cpa16(smb + SK0L + o, khl + (size_t)r * CH + g * 8);
        cpa16(smb + SVH0 + o, vhh + (size_t)r * LK + g * 8);
        cpa16(smb + SVL0 + o, vhl + (size_t)r * LK + g * 8);
    }
    CP_COMMIT();

    const int qr  = lane >> 2;
    const int c2  = (lane & 3) * 2;
    float* smc  = (float*)(sm + SMC);
    float* sM   = (float*)(sm + SRED);
    float* siZ  = (float*)(sm + SRED + 512);

    float M0 = -INFINITY, M1 = -INFINITY, Z0 = 0.f, Z1 = 0.f;
    float acc[8][4];
    #pragma unroll
    for (int t = 0; t < 8; t++)
        #pragma unroll
        for (int j = 0; j < 4; j++) acc[t][j] = 0.f;

    for (int cb = 0; cb < NCHK; cb++) {
        const int kb = cb * BK;

        CP_WAIT0();        // chunk cb resident
        __syncthreads();   // visible to all; prior readers of next-submit bufs done

        // ---- submit chunk cb+1 into the other buffers ----
        if (cb + 1 < NCHK) {
            const uint32_t kdh = smb + (((cb + 1) & 1) ? SK1H : SK0H);
            const uint32_t kdl = smb + (((cb + 1) & 1) ? SK1L : SK0L);
            const uint32_t vdh = smb + (((cb + 1) & 1) ? SVH1 : SVH0);
            const uint32_t vdl = smb + (((cb + 1) & 1) ? SVL1 : SVL0);
            const size_t kr0 = (size_t)(kb + BK);
            #pragma unroll
            for (int it = 0; it < 2; it++) {
                int idx = tid + it * TPB;
                int r = idx >> 3, g = idx & 7;
                uint32_t o = toff(r, g * 8);
                cpa16(kdh + o, khh + (kr0 + r) * CH + g * 8);
                cpa16(kdl + o, khl + (kr0 + r) * CH + g * 8);
                cpa16(vdh + o, vhh + (size_t)r * LK + kb + BK + g * 8);
                cpa16(vdl + o, vhl + (size_t)r * LK + kb + BK + g * 8);
            }
            CP_COMMIT();
        }

        // ---- mask -> bitmask reg ----
        uint32_t mb = 0;
        {
            const size_t off0 = (mrow0 + wrow + qr) * (size_t)LK + kb + c2;
            #pragma unroll
            for (int t = 0; t < 8; t++) {
                bool b00, b01, b10, b11;
                if (mkind == 1) {
                    int2 m0 = *(const int2*)((const int*)gmask + off0 + t * 8);
                    int2 m1 = *(const int2*)((const int*)gmask + off0 + t * 8 + 8 * LK);
                    b00 = m0.x != 0; b01 = m0.y != 0; b10 = m1.x != 0; b11 = m1.y != 0;
                } else if (mkind == 2) {
                    float2 m0 = *(const float2*)((const float*)gmask + off0 + t * 8);
                    float2 m1 = *(const float2*)((const float*)gmask + off0 + t * 8 + 8 * LK);
                    b00 = m0.x != 0.f; b01 = m0.y != 0.f; b10 = m1.x != 0.f; b11 = m1.y != 0.f;
                } else {
                    const unsigned char* mbp = (const unsigned char*)gmask + off0 + t * 8;
                    b00 = mbp[0] != 0; b01 = mbp[1] != 0;
                    b10 = mbp[8 * LK] != 0; b11 = mbp[8 * LK + 1] != 0;
                }
                mb |= ((uint32_t)b00 << (t * 4)) | ((uint32_t)b01 << (t * 4 + 1))
                    | ((uint32_t)b10 << (t * 4 + 2)) | ((uint32_t)b11 << (t * 4 + 3));
            }
        }

        // ---- MMA1: S = Qh*(Kh + Kl) ----
        float d[8][4];
        #pragma unroll
        for (int t = 0; t < 8; t++)
            #pragma unroll
            for (int j = 0; j < 4; j++) d[t][j] = 0.f;
        {
            const uint32_t kh_b = smb + ((cb & 1) ? SK1H : SK0H);
            const uint32_t kl_b = smb + ((cb & 1) ? SK1L : SK0L);
            int br = ((lane >> 4) & 1) * 8 + (lane & 7);
            int bc = ((lane >> 3) & 1) * 8;
            #pragma unroll
            for (int ks = 0; ks < 4; ks++) {
                #pragma unroll
                for (int tp = 0; tp < 4; tp++) {
                    uint32_t bh[4], bl[4];
                    uint32_t o = toff(tp * 16 + br, ks * 16 + bc);
                    ldsm4(bh, kh_b + o);
                    ldsm4(bl, kl_b + o);
                    mma16816(d[2*tp],   qf[ks], bh[0], bh[1]);
                    mma16816(d[2*tp+1], qf[ks], bh[2], bh[3]);
                    mma16816(d[2*tp],   qf[ks], bl[0], bl[1]);
                    mma16816(d[2*tp+1], qf[ks], bl[2], bl[3]);
                }
            }
        }

        // ---- mask ----
        #pragma unroll
        for (int t = 0; t < 8; t++) {
            d[t][0] = (mb >> (t * 4)     & 1u) ? d[t][0] : -1e30f;
            d[t][1] = (mb >> (t * 4 + 1) & 1u) ? d[t][1] : -1e30f;
            d[t][2] = (mb >> (t * 4 + 2) & 1u) ? d[t][2] : -1e30f;
            d[t][3] = (mb >> (t * 4 + 3) & 1u) ? d[t][3] : -1e30f;
        }

        // ---- chunk max per row ----
        float m0 = -INFINITY, m1 = -INFINITY;
        #pragma unroll
        for (int t = 0; t < 8; t++) {
            m0 = fmaxf(m0, fmaxf(d[t][0], d[t][1]));
            m1 = fmaxf(m1, fmaxf(d[t][2], d[t][3]));
        }
        m0 = fmaxf(m0, __shfl_xor_sync(0xffffffffu, m0, 1));
        m0 = fmaxf(m0, __shfl_xor_sync(0xffffffffu, m0, 2));
        m1 = fmaxf(m1, __shfl_xor_sync(0xffffffffu, m1, 1));
        m1 = fmaxf(m1, __shfl_xor_sync(0xffffffffu, m1, 2));

        const float Mn0 = fmaxf(M0, m0);
        const float Mn1 = fmaxf(M1, m1);
        const float rold0 = __expf(M0 - Mn0);
        const float rold1 = __expf(M1 - Mn1);

        // ---- u = exp(d - Mn), row sums ----
        float s0 = 0.f, s1 = 0.f;
        #pragma unroll
        for (int t = 0; t < 8; t++) {
            d[t][0] = __expf(d[t][0] - Mn0);
            d[t][1] = __expf(d[t][1] - Mn0);
            d[t][2] = __expf(d[t][2] - Mn1);
            d[t][3] = __expf(d[t][3] - Mn1);
            s0 += d[t][0] + d[t][1];
            s1 += d[t][2] + d[t][3];
        }
        s0 += __shfl_xor_sync(0xffffffffu, s0, 1);
        s0 += __shfl_xor_sync(0xffffffffu, s0, 2);
        s1 += __shfl_xor_sync(0xffffffffu, s1, 1);
        s1 += __shfl_xor_sync(0xffffffffu, s1, 2);

        Z0 = Z0 * rold0 + s0;  M0 = Mn0;
        Z1 = Z1 * rold1 + s1;  M1 = Mn1;

        // ---- write unnormalized u to w; record chunk max ----
        {
            float* w0 = wtile + (size_t)(wrow + qr) * LK + kb + c2;
            float* w1 = w0 + 8 * LK;
            #pragma unroll
            for (int t = 0; t < 8; t++) {
                *(float2*)(w0 + t * 8) = make_float2(d[t][0], d[t][1]);
                *(float2*)(w1 + t * 8) = make_float2(d[t][2], d[t][3]);
            }
            if ((lane & 3) == 0) {
                smc[cb * 128 + wrow + qr]     = Mn0;
                smc[cb * 128 + wrow + qr + 8] = Mn1;
            }
        }

        // ---- MMA2: acc = acc*rold + Ph*(Vh + Vl) ----
        #pragma unroll
        for (int t = 0; t < 8; t++) {
            acc[t][0] *= rold0; acc[t][1] *= rold0;
            acc[t][2] *= rold1; acc[t][3] *= rold1;
        }
        {
            const uint32_t vh_b = smb + ((cb & 1) ? SVH1 : SVH0);
            const uint32_t vl_b = smb + ((cb & 1) ? SVL1 : SVL0);
            int br = ((lane >> 4) & 1) * 8 + (lane & 7);
            int bc = ((lane >> 3) & 1) * 8;
            #pragma unroll
            for (int ks = 0; ks < 4; ks++) {
                uint32_t ph[4];
                ph[0] = pack2h(d[2*ks][0],   d[2*ks][1]);
                ph[1] = pack2h(d[2*ks][2],   d[2*ks][3]);
                ph[2] = pack2h(d[2*ks+1][0], d[2*ks+1][1]);
                ph[3] = pack2h(d[2*ks+1][2], d[2*ks+1][3]);
                #pragma unroll
                for (int tp = 0; tp < 4; tp++) {
                    uint32_t vh[4], vl[4];
                    uint32_t o = toff(tp * 16 + br, ks * 16 + bc);
                    ldsm4(vh, vh_b + o);
                    ldsm4(vl, vl_b + o);
                    mma16816(acc[2*tp],   ph, vh[0], vh[1]);
                    mma16816(acc[2*tp+1], ph, vh[2], vh[3]);
                    mma16816(acc[2*tp],   ph, vl[0], vl[1]);
                    mma16816(acc[2*tp+1], ph, vl[2], vl[3]);
                }
            }
        }
        // no end barrier: next iteration's top barrier provides the separation
    }

    // ---- write a = acc / Z  (a[c][q] layout) ----
    const float iZ0 = 1.0f / Z0;
    const float iZ1 = 1.0f / Z1;
    {
        #pragma unroll
        for (int t = 0; t < 8; t++) {
            int c = t * 8 + c2;
            float* a0 = ga + ((size_t)n * CH + c) * LQ + qbase + wrow;
            a0[qr]     = acc[t][0] * iZ0;
            a0[qr + 8] = acc[t][2] * iZ1;
            float* a1 = a0 + LQ;
            a1[qr]     = acc[t][1] * iZ0;
            a1[qr + 8] = acc[t][3] * iZ1;
        }
        if ((lane & 3) == 0) {
            sM[wrow + qr]     = M0;  siZ[wrow + qr]     = iZ0;
            sM[wrow + qr + 8] = M1;  siZ[wrow + qr + 8] = iZ1;
        }
    }
    __syncthreads();

    // ---- fused rescale: w *= exp(mc - M) / Z ----
    for (int i = tid; i < BQ * LK / 4; i += TPB) {
        int row = i >> 9;
        int j4  = i & 511;
        int cbk = j4 >> 4;
        float sc = __expf(smc[cbk * 128 + row] - sM[row]) * siZ[row];
        float4* p = (float4*)(wtile + (size_t)row * LK) + j4;
        float4 u = *p;
        u.x *= sc; u.y *= sc; u.z *= sc; u.w *= sc;
        *p = u;
    }
}

extern "C" void kernel_launch(void* const* d_in, const int* in_sizes, int n_in,
                              void* d_out, int out_size)
{
    const float* q = (const float*)d_in[0];
    const float* k = (const float*)d_in[1];
    const float* v = (const float*)d_in[2];
    const void*  mask = d_in[3];
    float* out = (float*)d_out;

    const long long A_ELEMS = (long long)NTOT * CH * LQ;   // 4,194,304
    const long long W_ELEMS = (long long)NTOT * LQ * LK;   // 134,217,728

    float* a_out;
    float* w_out;
    if ((long long)out_size >= A_ELEMS + W_ELEMS) {
        a_out = out;
        w_out = out + A_ELEMS;
    } else if ((long long)out_size >= W_ELEMS) {
        w_out = out;
        cudaGetSymbolAddress((void**)&a_out, g_a_scratch);
    } else {
        a_out = out;
        cudaGetSymbolAddress((void**)&w_out, g_w_scratch);
    }

    __half *q16, *k16h, *k16l, *v16h, *v16l;
    cudaGetSymbolAddress((void**)&q16,  g_q16);
    cudaGetSymbolAddress((void**)&k16h, g_k16h);
    cudaGetSymbolAddress((void**)&k16l, g_k16l);
    cudaGetSymbolAddress((void**)&v16h, g_v16h);
    cudaGetSymbolAddress((void**)&v16l, g_v16l);

    cudaFuncSetAttribute(attn_mma_kernel,
                         cudaFuncAttributeMaxDynamicSharedMemorySize, SMTOT);

    detect_mask_kind_kernel<<<1, 32>>>((const unsigned char*)mask);
    convert_kernel<<<dim3(32, NTOT, 3), 256>>>(q, k, v);

    dim3 grid(LQ / BQ, NTOT);
    attn_mma_kernel<<<grid, TPB, SMTOT>>>(q16, k16h, k16l, v16h, v16l,
                                          mask, a_out, w_out);
}

// round 14
// speedup vs baseline: 2.9608x; 1.3981x over previous
#include <cuda_runtime.h>
#include <cuda_fp16.h>
#include <math.h>
#include <stdint.h>

#define NTOT 32      // bs * heads
#define CH   64      // head dim
#define LQ   2048
#define LK   2048
#define BQ   128     // q rows per block
#define BK   64      // k cols per chunk
#define NCHK (LK / BK)   // 32
#define TPB  256

// -------- device scratch (no allocations allowed) --------
__device__ float  g_w_scratch[(size_t)NTOT * LQ * LK];
__device__ float  g_a_scratch[(size_t)NTOT * CH * LQ];
__device__ __half g_q16 [(size_t)NTOT * LQ * CH];   // [n][q][c], hi, pre-scaled
__device__ __half g_k16h[(size_t)NTOT * LK * CH];   // [n][k][c]
__device__ __half g_k16l[(size_t)NTOT * LK * CH];
__device__ __half g_v16h[(size_t)NTOT * CH * LK];   // [n][c][k]
__device__ __half g_v16l[(size_t)NTOT * CH * LK];
__device__ int    g_mask_kind;   // 0 u8, 1 i32, 2 f32

// Warp-parallel mask-dtype detection over the first 4096 bytes (~2us).
__global__ void detect_mask_kind_kernel(const uint4* __restrict__ m)
{
    const int lane = threadIdx.x;
    int a123 = 0, a01 = 0, sig = 0;
    #pragma unroll
    for (int i = lane; i < 256; i += 32) {
        uint4 v = m[i];
        uint32_t w[4] = {v.x, v.y, v.z, v.w};
        #pragma unroll
        for (int j = 0; j < 4; j++) {
            a123 |= (w[j] & 0xFFFFFF00u) != 0;   // any byte at r in {1,2,3}
            a01  |= (w[j] & 0x0000FFFFu) != 0;   // any byte at r in {0,1}
            sig  |= ((w[j] >> 24) == 0x3Fu);     // byte3 == 0x3F (float 1.0f)
        }
    }
    a123 = __any_sync(0xffffffffu, a123);
    a01  = __any_sync(0xffffffffu, a01);
    sig  = __any_sync(0xffffffffu, sig);
    if (lane == 0) {
        int kind;
        if (!a123)            kind = 1;   // int32 0/1
        else if (!a01 && sig) kind = 2;   // float32 0.0/1.0
        else                  kind = 0;   // byte bool
        g_mask_kind = kind;
    }
}

// ---- one-time convert: fp32 -> fp16 hi/lo with layout transform ----
__global__ void __launch_bounds__(256)
convert_kernel(const float* __restrict__ gq,
               const float* __restrict__ gk,
               const float* __restrict__ gv)
{
    __shared__ float ts[64][65];
    const int tid  = threadIdx.x;
    const int tile = blockIdx.x;   // 0..31
    const int n    = blockIdx.y;
    const int which = blockIdx.z;
    const size_t hb = (size_t)n * CH * LK;

    if (which == 2) {
        #pragma unroll
        for (int it = 0; it < 16; it++) {
            int flat = tile * 4096 + tid + it * 256;
            float v = gv[hb + flat];
            __half hv = __float2half_rn(v);
            g_v16h[hb + flat] = hv;
            g_v16l[hb + flat] = __float2half_rn(v - __half2float(hv));
        }
        return;
    }
    const float* src = (which == 0) ? gq : gk;
    #pragma unroll
    for (int it = 0; it < 16; it++) {
        int flat = tid + it * 256;
        int c = flat >> 6, x = flat & 63;
        ts[c][x] = src[hb + (size_t)c * LK + tile * 64 + x];
    }
    __syncthreads();
    #pragma unroll
    for (int it = 0; it < 16; it++) {
        int flat = tid + it * 256;
        int x = flat >> 6, c = flat & 63;
        float v = ts[c][x];
        size_t dst = hb + (size_t)(tile * 64 + x) * 64 + c;
        if (which == 0) {
            g_q16[dst] = __float2half_rn(v * 0.125f);
        } else {
            __half hv = __float2half_rn(v);
            g_k16h[dst] = hv;
            g_k16l[dst] = __float2half_rn(v - __half2float(hv));
        }
    }
}

// -------- helpers --------
__device__ __forceinline__ uint32_t sw128(uint32_t off) {
    return off ^ (((off >> 7) & 7) << 4);
}
__device__ __forceinline__ uint32_t toff(int r, int c) {
    return sw128((uint32_t)(r * 128 + c * 2));
}
__device__ __forceinline__ uint32_t smem_u32(const void* p) {
    uint32_t a;
    asm("{ .reg .u64 t; cvta.to.shared.u64 t, %1; cvt.u32.u64 %0, t; }" : "=r"(a) : "l"(p));
    return a;
}
__device__ __forceinline__ void ldsm4(uint32_t* r, uint32_t addr) {
    asm volatile("ldmatrix.sync.aligned.m8n8.x4.shared.b16 {%0,%1,%2,%3}, [%4];"
        : "=r"(r[0]), "=r"(r[1]), "=r"(r[2]), "=r"(r[3]) : "r"(addr));
}
__device__ __forceinline__ void mma16816(float* d, const uint32_t* a,
                                         uint32_t b0, uint32_t b1) {
    asm volatile("mma.sync.aligned.m16n8k16.row.col.f32.f16.f16.f32 "
        "{%0,%1,%2,%3}, {%4,%5,%6,%7}, {%8,%9}, {%0,%1,%2,%3};"
        : "+f"(d[0]), "+f"(d[1]), "+f"(d[2]), "+f"(d[3])
        : "r"(a[0]), "r"(a[1]), "r"(a[2]), "r"(a[3]), "r"(b0), "r"(b1));
}
__device__ __forceinline__ uint32_t pack2h(float x, float y) {
    __half2 h = __float22half2_rn(make_float2(x, y));
    return *(uint32_t*)&h;
}
__device__ __forceinline__ void cpa16(uint32_t dst, const void* src) {
    asm volatile("cp.async.cg.shared.global [%0], [%1], 16;" :: "r"(dst), "l"(src));
}
#define CP_COMMIT() asm volatile("cp.async.commit_group;" ::: "memory")
#define CP_WAIT0()  asm volatile("cp.async.wait_group 0;" ::: "memory")

// SMEM layout (bytes)
#define SK0H  0        //  8192  K buf0 hi [64 k][64 c]  (Q staged here pre-loop)
#define SK0L  8192     //  8192  K buf0 lo
#define SK1H  16384    //  8192  K buf1 hi
#define SK1L  24576    //  8192  K buf1 lo
#define SVH0  32768    //  8192  V buf0 hi [64 c][64 k]
#define SVL0  40960    //  8192  V buf0 lo
#define SVH1  49152    //  8192  V buf1 hi
#define SVL1  57344    //  8192  V buf1 lo
#define SMTOT 65536

extern "C" __global__ void __launch_bounds__(TPB, 2)
attn_mma_kernel(const __half* __restrict__ q16,
                const __half* __restrict__ k16h,
                const __half* __restrict__ k16l,
                const __half* __restrict__ v16h,
                const __half* __restrict__ v16l,
                const void* __restrict__ gmask,
                float* __restrict__ ga,
                float* __restrict__ gw)
{
    extern __shared__ __align__(1024) char sm[];
    const uint32_t smb = smem_u32(sm);

    const int tid   = threadIdx.x;
    const int warp  = tid >> 5;
    const int lane  = tid & 31;
    const int wrow  = warp * 16;
    const int n     = blockIdx.y;
    const int qbase = blockIdx.x * BQ;
    const int mkind = g_mask_kind;

    const __half* qh_g = q16 + ((size_t)n * LQ + qbase) * CH;     // [128][64]
    const __half* khh  = k16h + (size_t)n * LK * CH;              // [k][64]
    const __half* khl  = k16l + (size_t)n * LK * CH;
    const __half* vhh  = v16h + (size_t)n * CH * LK;              // [64][k]
    const __half* vhl  = v16l + (size_t)n * CH * LK;
    float* wtile = gw + ((size_t)n * LQ + qbase) * LK;
    const size_t mrow0 = (size_t)(n >> 4) * LQ + qbase;

    // ---- stage Q via cp.async into K buf0 region, load frags, free it ----
    #pragma unroll
    for (int it = 0; it < 4; it++) {
        int idx = tid + it * TPB;
        int r = idx >> 3, g = idx & 7;
        cpa16(smb + SK0H + toff(r, g * 8), qh_g + (size_t)r * CH + g * 8);
    }
    CP_COMMIT();
    CP_WAIT0();
    __syncthreads();

    uint32_t qf[4][4];
    {
        int r  = wrow + (lane & 15);
        int cg = (lane >> 4) * 8;
        #pragma unroll
        for (int ks = 0; ks < 4; ks++)
            ldsm4(qf[ks], smb + SK0H + toff(r, ks * 16 + cg));
    }
    __syncthreads();

    const int qr  = lane >> 2;
    const int c2  = (lane & 3) * 2;
    const int br  = ((lane >> 4) & 1) * 8 + (lane & 7);
    const int bc  = ((lane >> 3) & 1) * 8;

    float M0 = -INFINITY, M1 = -INFINITY, Z0 = 0.f, Z1 = 0.f;

    // =========================== PHASE A ===========================
    // Online (M, Z) over all chunks. MMA1 only, K-only staging, no stores.
    #pragma unroll
    for (int it = 0; it < 2; it++) {
        int idx = tid + it * TPB;
        int r = idx >> 3, g = idx & 7;
        uint32_t o = toff(r, g * 8);
        cpa16(smb + SK0H + o, khh + (size_t)r * CH + g * 8);
        cpa16(smb + SK0L + o, khl + (size_t)r * CH + g * 8);
    }
    CP_COMMIT();

    for (int cb = 0; cb < NCHK; cb++) {
        const int kb = cb * BK;
        CP_WAIT0();
        __syncthreads();
        if (cb + 1 < NCHK) {
            const uint32_t kdh = smb + (((cb + 1) & 1) ? SK1H : SK0H);
            const uint32_t kdl = smb + (((cb + 1) & 1) ? SK1L : SK0L);
            #pragma unroll
            for (int it = 0; it < 2; it++) {
                int idx = tid + it * TPB;
                int r = idx >> 3, g = idx & 7;
                uint32_t o = toff(r, g * 8);
                cpa16(kdh + o, khh + (size_t)(kb + BK + r) * CH + g * 8);
                cpa16(kdl + o, khl + (size_t)(kb + BK + r) * CH + g * 8);
            }
            CP_COMMIT();
        }

        // mask -> bitmask
        uint32_t mb = 0;
        {
            const size_t off0 = (mrow0 + wrow + qr) * (size_t)LK + kb + c2;
            #pragma unroll
            for (int t = 0; t < 8; t++) {
                bool b00, b01, b10, b11;
                if (mkind == 1) {
                    int2 m0 = *(const int2*)((const int*)gmask + off0 + t * 8);
                    int2 m1 = *(const int2*)((const int*)gmask + off0 + t * 8 + 8 * LK);
                    b00 = m0.x != 0; b01 = m0.y != 0; b10 = m1.x != 0; b11 = m1.y != 0;
                } else if (mkind == 2) {
                    float2 m0 = *(const float2*)((const float*)gmask + off0 + t * 8);
                    float2 m1 = *(const float2*)((const float*)gmask + off0 + t * 8 + 8 * LK);
                    b00 = m0.x != 0.f; b01 = m0.y != 0.f; b10 = m1.x != 0.f; b11 = m1.y != 0.f;
                } else {
                    const unsigned char* mbp = (const unsigned char*)gmask + off0 + t * 8;
                    b00 = mbp[0] != 0; b01 = mbp[1] != 0;
                    b10 = mbp[8 * LK] != 0; b11 = mbp[8 * LK + 1] != 0;
                }
                mb |= ((uint32_t)b00 << (t * 4)) | ((uint32_t)b01 << (t * 4 + 1))
                    | ((uint32_t)b10 << (t * 4 + 2)) | ((uint32_t)b11 << (t * 4 + 3));
            }
        }

        float d[8][4];
        #pragma unroll
        for (int t = 0; t < 8; t++)
            #pragma unroll
            for (int j = 0; j < 4; j++) d[t][j] = 0.f;
        {
            const uint32_t kh_b = smb + ((cb & 1) ? SK1H : SK0H);
            const uint32_t kl_b = smb + ((cb & 1) ? SK1L : SK0L);
            #pragma unroll
            for (int ks = 0; ks < 4; ks++) {
                #pragma unroll
                for (int tp = 0; tp < 4; tp++) {
                    uint32_t bh[4], bl[4];
                    uint32_t o = toff(tp * 16 + br, ks * 16 + bc);
                    ldsm4(bh, kh_b + o);
                    ldsm4(bl, kl_b + o);
                    mma16816(d[2*tp],   qf[ks], bh[0], bh[1]);
                    mma16816(d[2*tp+1], qf[ks], bh[2], bh[3]);
                    mma16816(d[2*tp],   qf[ks], bl[0], bl[1]);
                    mma16816(d[2*tp+1], qf[ks], bl[2], bl[3]);
                }
            }
        }

        #pragma unroll
        for (int t = 0; t < 8; t++) {
            d[t][0] = (mb >> (t * 4)     & 1u) ? d[t][0] : -1e30f;
            d[t][1] = (mb >> (t * 4 + 1) & 1u) ? d[t][1] : -1e30f;
            d[t][2] = (mb >> (t * 4 + 2) & 1u) ? d[t][2] : -1e30f;
            d[t][3] = (mb >> (t * 4 + 3) & 1u) ? d[t][3] : -1e30f;
        }

        float m0 = -INFINITY, m1 = -INFINITY;
        #pragma unroll
        for (int t = 0; t < 8; t++) {
            m0 = fmaxf(m0, fmaxf(d[t][0], d[t][1]));
            m1 = fmaxf(m1, fmaxf(d[t][2], d[t][3]));
        }
        m0 = fmaxf(m0, __shfl_xor_sync(0xffffffffu, m0, 1));
        m0 = fmaxf(m0, __shfl_xor_sync(0xffffffffu, m0, 2));
        m1 = fmaxf(m1, __shfl_xor_sync(0xffffffffu, m1, 1));
        m1 = fmaxf(m1, __shfl_xor_sync(0xffffffffu, m1, 2));

        const float Mn0 = fmaxf(M0, m0);
        const float Mn1 = fmaxf(M1, m1);
        const float rold0 = __expf(M0 - Mn0);
        const float rold1 = __expf(M1 - Mn1);

        float s0 = 0.f, s1 = 0.f;
        #pragma unroll
        for (int t = 0; t < 8; t++) {
            s0 += __expf(d[t][0] - Mn0) + __expf(d[t][1] - Mn0);
            s1 += __expf(d[t][2] - Mn1) + __expf(d[t][3] - Mn1);
        }
        s0 += __shfl_xor_sync(0xffffffffu, s0, 1);
        s0 += __shfl_xor_sync(0xffffffffu, s0, 2);
        s1 += __shfl_xor_sync(0xffffffffu, s1, 1);
        s1 += __shfl_xor_sync(0xffffffffu, s1, 2);

        Z0 = Z0 * rold0 + s0;  M0 = Mn0;
        Z1 = Z1 * rold1 + s1;  M1 = Mn1;
    }

    const float iZ0 = 1.0f / Z0;
    const float iZ1 = 1.0f / Z1;

    // =========================== PHASE B ===========================
    // Recompute S, write final normalized w ONCE, accumulate a = P V.
    float acc[8][4];
    #pragma unroll
    for (int t = 0; t < 8; t++)
        #pragma unroll
        for (int j = 0; j < 4; j++) acc[t][j] = 0.f;

    #pragma unroll
    for (int it = 0; it < 2; it++) {
        int idx = tid + it * TPB;
        int r = idx >> 3, g = idx & 7;
        uint32_t o = toff(r, g * 8);
        cpa16(smb + SK0H + o, khh + (size_t)r * CH + g * 8);
        cpa16(smb + SK0L + o, khl + (size_t)r * CH + g * 8);
        cpa16(smb + SVH0 + o, vhh + (size_t)r * LK + g * 8);
        cpa16(smb + SVL0 + o, vhl + (size_t)r * LK + g * 8);
    }
    CP_COMMIT();

    for (int cb = 0; cb < NCHK; cb++) {
        const int kb = cb * BK;
        CP_WAIT0();
        __syncthreads();
        if (cb + 1 < NCHK) {
            const uint32_t kdh = smb + (((cb + 1) & 1) ? SK1H : SK0H);
            const uint32_t kdl = smb + (((cb + 1) & 1) ? SK1L : SK0L);
            const uint32_t vdh = smb + (((cb + 1) & 1) ? SVH1 : SVH0);
            const uint32_t vdl = smb + (((cb + 1) & 1) ? SVL1 : SVL0);
            #pragma unroll
            for (int it = 0; it < 2; it++) {
                int idx = tid + it * TPB;
                int r = idx >> 3, g = idx & 7;
                uint32_t o = toff(r, g * 8);
                cpa16(kdh + o, khh + (size_t)(kb + BK + r) * CH + g * 8);
                cpa16(kdl + o, khl + (size_t)(kb + BK + r) * CH + g * 8);
                cpa16(vdh + o, vhh + (size_t)r * LK + kb + BK + g * 8);
                cpa16(vdl + o, vhl + (size_t)r * LK + kb + BK + g * 8);
            }
            CP_COMMIT();
        }

        uint32_t mb = 0;
        {
            const size_t off0 = (mrow0 + wrow + qr) * (size_t)LK + kb + c2;
            #pragma unroll
            for (int t = 0; t < 8; t++) {
                bool b00, b01, b10, b11;
                if (mkind == 1) {
                    int2 m0 = *(const int2*)((const int*)gmask + off0 + t * 8);
                    int2 m1 = *(const int2*)((const int*)gmask + off0 + t * 8 + 8 * LK);
                    b00 = m0.x != 0; b01 = m0.y != 0; b10 = m1.x != 0; b11 = m1.y != 0;
                } else if (mkind == 2) {
                    float2 m0 = *(const float2*)((const float*)gmask + off0 + t * 8);
                    float2 m1 = *(const float2*)((const float*)gmask + off0 + t * 8 + 8 * LK);
                    b00 = m0.x != 0.f; b01 = m0.y != 0.f; b10 = m1.x != 0.f; b11 = m1.y != 0.f;
                } else {
                    const unsigned char* mbp = (const unsigned char*)gmask + off0 + t * 8;
                    b00 = mbp[0] != 0; b01 = mbp[1] != 0;
                    b10 = mbp[8 * LK] != 0; b11 = mbp[8 * LK + 1] != 0;
                }
                mb |= ((uint32_t)b00 << (t * 4)) | ((uint32_t)b01 << (t * 4 + 1))
                    | ((uint32_t)b10 << (t * 4 + 2)) | ((uint32_t)b11 << (t * 4 + 3));
            }
        }

        float d[8][4];
        #pragma unroll
        for (int t = 0; t < 8; t++)
            #pragma unroll
            for (int j = 0; j < 4; j++) d[t][j] = 0.f;
        {
            const uint32_t kh_b = smb + ((cb & 1) ? SK1H : SK0H);
            const uint32_t kl_b = smb + ((cb & 1) ? SK1L : SK0L);
            #pragma unroll
            for (int ks = 0; ks < 4; ks++) {
                #pragma unroll
                for (int tp = 0; tp < 4; tp++) {
                    uint32_t bh[4], bl[4];
                    uint32_t o = toff(tp * 16 + br, ks * 16 + bc);
                    ldsm4(bh, kh_b + o);
                    ldsm4(bl, kl_b + o);
                    mma16816(d[2*tp],   qf[ks], bh[0], bh[1]);
                    mma16816(d[2*tp+1], qf[ks], bh[2], bh[3]);
                    mma16816(d[2*tp],   qf[ks], bl[0], bl[1]);
                    mma16816(d[2*tp+1], qf[ks], bl[2], bl[3]);
                }
            }
        }

        // p = exp(S - M) * invZ  (masked -> 0 exactly via -1e30)
        #pragma unroll
        for (int t = 0; t < 8; t++) {
            d[t][0] = (mb >> (t * 4)     & 1u) ? __expf(d[t][0] - M0) * iZ0 : 0.f;
            d[t][1] = (mb >> (t * 4 + 1) & 1u) ? __expf(d[t][1] - M0) * iZ0 : 0.f;
            d[t][2] = (mb >> (t * 4 + 2) & 1u) ? __expf(d[t][2] - M1) * iZ1 : 0.f;
            d[t][3] = (mb >> (t * 4 + 3) & 1u) ? __expf(d[t][3] - M1) * iZ1 : 0.f;
        }

        // write FINAL w (single pass, no rescale tail)
        {
            float* w0 = wtile + (size_t)(wrow + qr) * LK + kb + c2;
            float* w1 = w0 + 8 * LK;
            #pragma unroll
            for (int t = 0; t < 8; t++) {
                *(float2*)(w0 + t * 8) = make_float2(d[t][0], d[t][1]);
                *(float2*)(w1 + t * 8) = make_float2(d[t][2], d[t][3]);
            }
        }

        // MMA2: acc += P * V  (no rescale — P is final)
        {
            const uint32_t vh_b = smb + ((cb & 1) ? SVH1 : SVH0);
            const uint32_t vl_b = smb + ((cb & 1) ? SVL1 : SVL0);
            #pragma unroll
            for (int ks = 0; ks < 4; ks++) {
                uint32_t ph[4];
                ph[0] = pack2h(d[2*ks][0],   d[2*ks][1]);
                ph[1] = pack2h(d[2*ks][2],   d[2*ks][3]);
                ph[2] = pack2h(d[2*ks+1][0], d[2*ks+1][1]);
                ph[3] = pack2h(d[2*ks+1][2], d[2*ks+1][3]);
                #pragma unroll
                for (int tp = 0; tp < 4; tp++) {
                    uint32_t vh[4], vl[4];
                    uint32_t o = toff(tp * 16 + br, ks * 16 + bc);
                    ldsm4(vh, vh_b + o);
                    ldsm4(vl, vl_b + o);
                    mma16816(acc[2*tp],   ph, vh[0], vh[1]);
                    mma16816(acc[2*tp+1], ph, vh[2], vh[3]);
                    mma16816(acc[2*tp],   ph, vl[0], vl[1]);
                    mma16816(acc[2*tp+1], ph, vl[2], vl[3]);
                }
            }
        }
    }

    // ---- write a = acc (already normalized), [c][q] layout ----
    #pragma unroll
    for (int t = 0; t < 8; t++) {
        int c = t * 8 + c2;
        float* a0 = ga + ((size_t)n * CH + c) * LQ + qbase + wrow;
        a0[qr]     = acc[t][0];
        a0[qr + 8] = acc[t][2];
        float* a1 = a0 + LQ;
        a1[qr]     = acc[t][1];
        a1[qr + 8] = acc[t][3];
    }
}

extern "C" void kernel_launch(void* const* d_in, const int* in_sizes, int n_in,
                              void* d_out, int out_size)
{
    const float* q = (const float*)d_in[0];
    const float* k = (const float*)d_in[1];
    const float* v = (const float*)d_in[2];
    const void*  mask = d_in[3];
    float* out = (float*)d_out;

    const long long A_ELEMS = (long long)NTOT * CH * LQ;   // 4,194,304
    const long long W_ELEMS = (long long)NTOT * LQ * LK;   // 134,217,728

    float* a_out;
    float* w_out;
    if ((long long)out_size >= A_ELEMS + W_ELEMS) {
        a_out = out;
        w_out = out + A_ELEMS;
    } else if ((long long)out_size >= W_ELEMS) {
        w_out = out;
        cudaGetSymbolAddress((void**)&a_out, g_a_scratch);
    } else {
        a_out = out;
        cudaGetSymbolAddress((void**)&w_out, g_w_scratch);
    }

    __half *q16, *k16h, *k16l, *v16h, *v16l;
    cudaGetSymbolAddress((void**)&q16,  g_q16);
    cudaGetSymbolAddress((void**)&k16h, g_k16h);
    cudaGetSymbolAddress((void**)&k16l, g_k16l);
    cudaGetSymbolAddress((void**)&v16h, g_v16h);
    cudaGetSymbolAddress((void**)&v16l, g_v16l);

    cudaFuncSetAttribute(attn_mma_kernel,
                         cudaFuncAttributeMaxDynamicSharedMemorySize, SMTOT);

    detect_mask_kind_kernel<<<1, 32>>>((const uint4*)mask);
    convert_kernel<<<dim3(32, NTOT, 3), 256>>>(q, k, v);

    dim3 grid(LQ / BQ, NTOT);
    attn_mma_kernel<<<grid, TPB, SMTOT>>>(q16, k16h, k16l, v16h, v16l,
                                          mask, a_out, w_out);
}

// round 15
// speedup vs baseline: 3.1973x; 1.0799x over previous
#include <cuda_runtime.h>
#include <cuda_fp16.h>
#include <math.h>
#include <stdint.h>

#define NTOT 32      // bs * heads
#define CH   64      // head dim
#define LQ   2048
#define LK   2048
#define BQ   128     // q rows per block
#define BK   64      // k cols per chunk
#define NCHK (LK / BK)   // 32
#define TPB  256

// -------- device scratch (no allocations allowed) --------
__device__ float  g_w_scratch[(size_t)NTOT * LQ * LK];
__device__ float  g_a_scratch[(size_t)NTOT * CH * LQ];
__device__ __half g_q16 [(size_t)NTOT * LQ * CH];   // [n][q][c], hi, pre-scaled
__device__ __half g_k16h[(size_t)NTOT * LK * CH];   // [n][k][c]
__device__ __half g_k16l[(size_t)NTOT * LK * CH];
__device__ __half g_v16h[(size_t)NTOT * CH * LK];   // [n][c][k]
__device__ __half g_v16l[(size_t)NTOT * CH * LK];
__device__ int    g_mask_kind;   // 0 u8, 1 i32, 2 f32

__global__ void detect_mask_kind_kernel(const uint4* __restrict__ m)
{
    const int lane = threadIdx.x;
    int a123 = 0, a01 = 0, sig = 0;
    #pragma unroll
    for (int i = lane; i < 256; i += 32) {
        uint4 v = m[i];
        uint32_t w[4] = {v.x, v.y, v.z, v.w};
        #pragma unroll
        for (int j = 0; j < 4; j++) {
            a123 |= (w[j] & 0xFFFFFF00u) != 0;
            a01  |= (w[j] & 0x0000FFFFu) != 0;
            sig  |= ((w[j] >> 24) == 0x3Fu);
        }
    }
    a123 = __any_sync(0xffffffffu, a123);
    a01  = __any_sync(0xffffffffu, a01);
    sig  = __any_sync(0xffffffffu, sig);
    if (lane == 0) {
        int kind;
        if (!a123)            kind = 1;
        else if (!a01 && sig) kind = 2;
        else                  kind = 0;
        g_mask_kind = kind;
    }
}

// ---- one-time convert: fp32 -> fp16 hi/lo with layout transform ----
__global__ void __launch_bounds__(256)
convert_kernel(const float* __restrict__ gq,
               const float* __restrict__ gk,
               const float* __restrict__ gv)
{
    __shared__ float ts[64][65];
    const int tid  = threadIdx.x;
    const int tile = blockIdx.x;   // 0..31
    const int n    = blockIdx.y;
    const int which = blockIdx.z;
    const size_t hb = (size_t)n * CH * LK;

    if (which == 2) {
        #pragma unroll
        for (int it = 0; it < 16; it++) {
            int flat = tile * 4096 + tid + it * 256;
            float v = gv[hb + flat];
            __half hv = __float2half_rn(v);
            g_v16h[hb + flat] = hv;
            g_v16l[hb + flat] = __float2half_rn(v - __half2float(hv));
        }
        return;
    }
    const float* src = (which == 0) ? gq : gk;
    #pragma unroll
    for (int it = 0; it < 16; it++) {
        int flat = tid + it * 256;
        int c = flat >> 6, x = flat & 63;
        ts[c][x] = src[hb + (size_t)c * LK + tile * 64 + x];
    }
    __syncthreads();
    #pragma unroll
    for (int it = 0; it < 16; it++) {
        int flat = tid + it * 256;
        int x = flat >> 6, c = flat & 63;
        float v = ts[c][x];
        size_t dst = hb + (size_t)(tile * 64 + x) * 64 + c;
        if (which == 0) {
            g_q16[dst] = __float2half_rn(v * 0.125f);
        } else {
            __half hv = __float2half_rn(v);
            g_k16h[dst] = hv;
            g_k16l[dst] = __float2half_rn(v - __half2float(hv));
        }
    }
}

// -------- helpers --------
__device__ __forceinline__ uint32_t sw128(uint32_t off) {
    return off ^ (((off >> 7) & 7) << 4);
}
__device__ __forceinline__ uint32_t toff(int r, int c) {
    return sw128((uint32_t)(r * 128 + c * 2));
}
__device__ __forceinline__ uint32_t smem_u32(const void* p) {
    uint32_t a;
    asm("{ .reg .u64 t; cvta.to.shared.u64 t, %1; cvt.u32.u64 %0, t; }" : "=r"(a) : "l"(p));
    return a;
}
__device__ __forceinline__ void ldsm4(uint32_t* r, uint32_t addr) {
    asm volatile("ldmatrix.sync.aligned.m8n8.x4.shared.b16 {%0,%1,%2,%3}, [%4];"
        : "=r"(r[0]), "=r"(r[1]), "=r"(r[2]), "=r"(r[3]) : "r"(addr));
}
__device__ __forceinline__ void mma16816(float* d, const uint32_t* a,
                                         uint32_t b0, uint32_t b1) {
    asm volatile("mma.sync.aligned.m16n8k16.row.col.f32.f16.f16.f32 "
        "{%0,%1,%2,%3}, {%4,%5,%6,%7}, {%8,%9}, {%0,%1,%2,%3};"
        : "+f"(d[0]), "+f"(d[1]), "+f"(d[2]), "+f"(d[3])
        : "r"(a[0]), "r"(a[1]), "r"(a[2]), "r"(a[3]), "r"(b0), "r"(b1));
}
__device__ __forceinline__ uint32_t pack2h(float x, float y) {
    __half2 h = __float22half2_rn(make_float2(x, y));
    return *(uint32_t*)&h;
}
__device__ __forceinline__ void cpa16(uint32_t dst, const void* src) {
    asm volatile("cp.async.cg.shared.global [%0], [%1], 16;" :: "r"(dst), "l"(src));
}
#define CP_COMMIT() asm volatile("cp.async.commit_group;" ::: "memory")
#define CP_WAIT0()  asm volatile("cp.async.wait_group 0;" ::: "memory")

// SMEM layout (bytes)
// Phase A: two 16KB K-hi buffers at 0 and 16384 (128 k-rows each).
// Phase B: SK0H/SK0L/SK1H/SK1L + V buffers as before.
#define SK0H  0        //  8192  K buf0 hi [64 k][64 c]  (Q staged here pre-loop)
#define SK0L  8192     //  8192  K buf0 lo
#define SK1H  16384    //  8192  K buf1 hi
#define SK1L  24576    //  8192  K buf1 lo
#define SVH0  32768    //  8192  V buf0 hi [64 c][64 k]
#define SVL0  40960    //  8192  V buf0 lo
#define SVH1  49152    //  8192  V buf1 hi
#define SVL1  57344    //  8192  V buf1 lo
#define SMTOT 65536

extern "C" __global__ void __launch_bounds__(TPB, 2)
attn_mma_kernel(const __half* __restrict__ q16,
                const __half* __restrict__ k16h,
                const __half* __restrict__ k16l,
                const __half* __restrict__ v16h,
                const __half* __restrict__ v16l,
                const void* __restrict__ gmask,
                float* __restrict__ ga,
                float* __restrict__ gw)
{
    extern __shared__ __align__(1024) char sm[];
    const uint32_t smb = smem_u32(sm);

    const int tid   = threadIdx.x;
    const int warp  = tid >> 5;
    const int lane  = tid & 31;
    const int wrow  = warp * 16;
    const int n     = blockIdx.y;
    const int qbase = blockIdx.x * BQ;
    const int mkind = g_mask_kind;

    const __half* qh_g = q16 + ((size_t)n * LQ + qbase) * CH;
    const __half* khh  = k16h + (size_t)n * LK * CH;
    const __half* khl  = k16l + (size_t)n * LK * CH;
    const __half* vhh  = v16h + (size_t)n * CH * LK;
    const __half* vhl  = v16l + (size_t)n * CH * LK;
    float* wtile = gw + ((size_t)n * LQ + qbase) * LK;
    const size_t mrow0 = (size_t)(n >> 4) * LQ + qbase;

    // ---- stage Q, load fragments ----
    #pragma unroll
    for (int it = 0; it < 4; it++) {
        int idx = tid + it * TPB;
        int r = idx >> 3, g = idx & 7;
        cpa16(smb + SK0H + toff(r, g * 8), qh_g + (size_t)r * CH + g * 8);
    }
    CP_COMMIT();
    CP_WAIT0();
    __syncthreads();

    uint32_t qf[4][4];
    {
        int r  = wrow + (lane & 15);
        int cg = (lane >> 4) * 8;
        #pragma unroll
        for (int ks = 0; ks < 4; ks++)
            ldsm4(qf[ks], smb + SK0H + toff(r, ks * 16 + cg));
    }
    __syncthreads();

    const int qr  = lane >> 2;
    const int c2  = (lane & 3) * 2;
    const int br  = ((lane >> 4) & 1) * 8 + (lane & 7);
    const int bc  = ((lane >> 3) & 1) * 8;

    float M0 = -INFINITY, M1 = -INFINITY, Z0 = 0.f, Z1 = 0.f;

    // =========================== PHASE A ===========================
    // (M, Z) only. K HI ONLY, staged as 128-row pairs, double-buffered.
    // Buffer p&1 at smb + (p&1)*16384, holds k rows [p*128, p*128+128).
    #pragma unroll
    for (int it = 0; it < 4; it++) {
        int idx = tid + it * TPB;           // 0..1023
        int r = idx >> 3, g = idx & 7;
        cpa16(smb + toff(r, g * 8), khh + (size_t)r * CH + g * 8);
    }
    CP_COMMIT();

    for (int cb = 0; cb < NCHK; cb++) {
        const int kb = cb * BK;
        const int pair = cb >> 1;

        if ((cb & 1) == 0) {
            CP_WAIT0();
            __syncthreads();
            if (pair + 1 < NCHK / 2) {      // stage next 128-row pair
                const uint32_t dst = smb + ((pair + 1) & 1) * 16384;
                const size_t kr0 = (size_t)(pair + 1) * 128;
                #pragma unroll
                for (int it = 0; it < 4; it++) {
                    int idx = tid + it * TPB;
                    int r = idx >> 3, g = idx & 7;
                    cpa16(dst + toff(r, g * 8), khh + (kr0 + r) * CH + g * 8);
                }
                CP_COMMIT();
            }
        }

        // mask -> bitmask
        uint32_t mb = 0;
        {
            const size_t off0 = (mrow0 + wrow + qr) * (size_t)LK + kb + c2;
            #pragma unroll
            for (int t = 0; t < 8; t++) {
                bool b00, b01, b10, b11;
                if (mkind == 1) {
                    int2 m0 = *(const int2*)((const int*)gmask + off0 + t * 8);
                    int2 m1 = *(const int2*)((const int*)gmask + off0 + t * 8 + 8 * LK);
                    b00 = m0.x != 0; b01 = m0.y != 0; b10 = m1.x != 0; b11 = m1.y != 0;
                } else if (mkind == 2) {
                    float2 m0 = *(const float2*)((const float*)gmask + off0 + t * 8);
                    float2 m1 = *(const float2*)((const float*)gmask + off0 + t * 8 + 8 * LK);
                    b00 = m0.x != 0.f; b01 = m0.y != 0.f; b10 = m1.x != 0.f; b11 = m1.y != 0.f;
                } else {
                    const unsigned char* mbp = (const unsigned char*)gmask + off0 + t * 8;
                    b00 = mbp[0] != 0; b01 = mbp[1] != 0;
                    b10 = mbp[8 * LK] != 0; b11 = mbp[8 * LK + 1] != 0;
                }
                mb |= ((uint32_t)b00 << (t * 4)) | ((uint32_t)b01 << (t * 4 + 1))
                    | ((uint32_t)b10 << (t * 4 + 2)) | ((uint32_t)b11 << (t * 4 + 3));
            }
        }

        // MMA1 (hi only)
        float d[8][4];
        #pragma unroll
        for (int t = 0; t < 8; t++)
            #pragma unroll
            for (int j = 0; j < 4; j++) d[t][j] = 0.f;
        {
            const uint32_t kbuf = smb + (pair & 1) * 16384;
            const int roff = (cb & 1) * 64;
            #pragma unroll
            for (int ks = 0; ks < 4; ks++) {
                #pragma unroll
                for (int tp = 0; tp < 4; tp++) {
                    uint32_t bh[4];
                    ldsm4(bh, kbuf + toff(roff + tp * 16 + br, ks * 16 + bc));
                    mma16816(d[2*tp],   qf[ks], bh[0], bh[1]);
                    mma16816(d[2*tp+1], qf[ks], bh[2], bh[3]);
                }
            }
        }

        #pragma unroll
        for (int t = 0; t < 8; t++) {
            d[t][0] = (mb >> (t * 4)     & 1u) ? d[t][0] : -1e30f;
            d[t][1] = (mb >> (t * 4 + 1) & 1u) ? d[t][1] : -1e30f;
            d[t][2] = (mb >> (t * 4 + 2) & 1u) ? d[t][2] : -1e30f;
            d[t][3] = (mb >> (t * 4 + 3) & 1u) ? d[t][3] : -1e30f;
        }

        float m0 = -INFINITY, m1 = -INFINITY;
        #pragma unroll
        for (int t = 0; t < 8; t++) {
            m0 = fmaxf(m0, fmaxf(d[t][0], d[t][1]));
            m1 = fmaxf(m1, fmaxf(d[t][2], d[t][3]));
        }
        m0 = fmaxf(m0, __shfl_xor_sync(0xffffffffu, m0, 1));
        m0 = fmaxf(m0, __shfl_xor_sync(0xffffffffu, m0, 2));
        m1 = fmaxf(m1, __shfl_xor_sync(0xffffffffu, m1, 1));
        m1 = fmaxf(m1, __shfl_xor_sync(0xffffffffu, m1, 2));

        const float Mn0 = fmaxf(M0, m0);
        const float Mn1 = fmaxf(M1, m1);
        const float rold0 = __expf(M0 - Mn0);
        const float rold1 = __expf(M1 - Mn1);

        float s0 = 0.f, s1 = 0.f;
        #pragma unroll
        for (int t = 0; t < 8; t++) {
            s0 += __expf(d[t][0] - Mn0) + __expf(d[t][1] - Mn0);
            s1 += __expf(d[t][2] - Mn1) + __expf(d[t][3] - Mn1);
        }
        s0 += __shfl_xor_sync(0xffffffffu, s0, 1);
        s0 += __shfl_xor_sync(0xffffffffu, s0, 2);
        s1 += __shfl_xor_sync(0xffffffffu, s1, 1);
        s1 += __shfl_xor_sync(0xffffffffu, s1, 2);

        Z0 = Z0 * rold0 + s0;  M0 = Mn0;
        Z1 = Z1 * rold1 + s1;  M1 = Mn1;
    }

    const float iZ0 = 1.0f / Z0;
    const float iZ1 = 1.0f / Z1;

    // =========================== PHASE B ===========================
    // Recompute S (2-term), write final w ONCE, accumulate a = P V.
    float acc[8][4];
    #pragma unroll
    for (int t = 0; t < 8; t++)
        #pragma unroll
        for (int j = 0; j < 4; j++) acc[t][j] = 0.f;

    // Initial staging into buf0 + V0. Safe without barrier: phase A's final
    // chunk (cb=31) reads buf1 (16384..32768); these writes hit 0..16384 and
    // the V region, whose last readers retired before the cb=30 barrier.
    #pragma unroll
    for (int it = 0; it < 2; it++) {
        int idx = tid + it * TPB;
        int r = idx >> 3, g = idx & 7;
        uint32_t o = toff(r, g * 8);
        cpa16(smb + SK0H + o, khh + (size_t)r * CH + g * 8);
        cpa16(smb + SK0L + o, khl + (size_t)r * CH + g * 8);
        cpa16(smb + SVH0 + o, vhh + (size_t)r * LK + g * 8);
        cpa16(smb + SVL0 + o, vhl + (size_t)r * LK + g * 8);
    }
    CP_COMMIT();

    for (int cb = 0; cb < NCHK; cb++) {
        const int kb = cb * BK;
        CP_WAIT0();
        __syncthreads();
        if (cb + 1 < NCHK) {
            const uint32_t kdh = smb + (((cb + 1) & 1) ? SK1H : SK0H);
            const uint32_t kdl = smb + (((cb + 1) & 1) ? SK1L : SK0L);
            const uint32_t vdh = smb + (((cb + 1) & 1) ? SVH1 : SVH0);
            const uint32_t vdl = smb + (((cb + 1) & 1) ? SVL1 : SVL0);
            #pragma unroll
            for (int it = 0; it < 2; it++) {
                int idx = tid + it * TPB;
                int r = idx >> 3, g = idx & 7;
                uint32_t o = toff(r, g * 8);
                cpa16(kdh + o, khh + (size_t)(kb + BK + r) * CH + g * 8);
                cpa16(kdl + o, khl + (size_t)(kb + BK + r) * CH + g * 8);
                cpa16(vdh + o, vhh + (size_t)r * LK + kb + BK + g * 8);
                cpa16(vdl + o, vhl + (size_t)r * LK + kb + BK + g * 8);
            }
            CP_COMMIT();
        }

        uint32_t mb = 0;
        {
            const size_t off0 = (mrow0 + wrow + qr) * (size_t)LK + kb + c2;
            #pragma unroll
            for (int t = 0; t < 8; t++) {
                bool b00, b01, b10, b11;
                if (mkind == 1) {
                    int2 m0 = *(const int2*)((const int*)gmask + off0 + t * 8);
                    int2 m1 = *(const int2*)((const int*)gmask + off0 + t * 8 + 8 * LK);
                    b00 = m0.x != 0; b01 = m0.y != 0; b10 = m1.x != 0; b11 = m1.y != 0;
                } else if (mkind == 2) {
                    float2 m0 = *(const float2*)((const float*)gmask + off0 + t * 8);
                    float2 m1 = *(const float2*)((const float*)gmask + off0 + t * 8 + 8 * LK);
                    b00 = m0.x != 0.f; b01 = m0.y != 0.f; b10 = m1.x != 0.f; b11 = m1.y != 0.f;
                } else {
                    const unsigned char* mbp = (const unsigned char*)gmask + off0 + t * 8;
                    b00 = mbp[0] != 0; b01 = mbp[1] != 0;
                    b10 = mbp[8 * LK] != 0; b11 = mbp[8 * LK + 1] != 0;
                }
                mb |= ((uint32_t)b00 << (t * 4)) | ((uint32_t)b01 << (t * 4 + 1))
                    | ((uint32_t)b10 << (t * 4 + 2)) | ((uint32_t)b11 << (t * 4 + 3));
            }
        }

        float d[8][4];
        #pragma unroll
        for (int t = 0; t < 8; t++)
            #pragma unroll
            for (int j = 0; j < 4; j++) d[t][j] = 0.f;
        {
            const uint32_t kh_b = smb + ((cb & 1) ? SK1H : SK0H);
            const uint32_t kl_b = smb + ((cb & 1) ? SK1L : SK0L);
            #pragma unroll
            for (int ks = 0; ks < 4; ks++) {
                #pragma unroll
                for (int tp = 0; tp < 4; tp++) {
                    uint32_t bh[4], bl[4];
                    uint32_t o = toff(tp * 16 + br, ks * 16 + bc);
                    ldsm4(bh, kh_b + o);
                    ldsm4(bl, kl_b + o);
                    mma16816(d[2*tp],   qf[ks], bh[0], bh[1]);
                    mma16816(d[2*tp+1], qf[ks], bh[2], bh[3]);
                    mma16816(d[2*tp],   qf[ks], bl[0], bl[1]);
                    mma16816(d[2*tp+1], qf[ks], bl[2], bl[3]);
                }
            }
        }

        // p = exp(S - M) * invZ  (masked -> exactly 0)
        #pragma unroll
        for (int t = 0; t < 8; t++) {
            d[t][0] = (mb >> (t * 4)     & 1u) ? __expf(d[t][0] - M0) * iZ0 : 0.f;
            d[t][1] = (mb >> (t * 4 + 1) & 1u) ? __expf(d[t][1] - M0) * iZ0 : 0.f;
            d[t][2] = (mb >> (t * 4 + 2) & 1u) ? __expf(d[t][2] - M1) * iZ1 : 0.f;
            d[t][3] = (mb >> (t * 4 + 3) & 1u) ? __expf(d[t][3] - M1) * iZ1 : 0.f;
        }

        // write FINAL w
        {
            float* w0 = wtile + (size_t)(wrow + qr) * LK + kb + c2;
            float* w1 = w0 + 8 * LK;
            #pragma unroll
            for (int t = 0; t < 8; t++) {
                *(float2*)(w0 + t * 8) = make_float2(d[t][0], d[t][1]);
                *(float2*)(w1 + t * 8) = make_float2(d[t][2], d[t][3]);
            }
        }

        // MMA2: acc += P * V
        {
            const uint32_t vh_b = smb + ((cb & 1) ? SVH1 : SVH0);
            const uint32_t vl_b = smb + ((cb & 1) ? SVL1 : SVL0);
            #pragma unroll
            for (int ks = 0; ks < 4; ks++) {
                uint32_t ph[4];
                ph[0] = pack2h(d[2*ks][0],   d[2*ks][1]);
                ph[1] = pack2h(d[2*ks][2],   d[2*ks][3]);
                ph[2] = pack2h(d[2*ks+1][0], d[2*ks+1][1]);
                ph[3] = pack2h(d[2*ks+1][2], d[2*ks+1][3]);
                #pragma unroll
                for (int tp = 0; tp < 4; tp++) {
                    uint32_t vh[4], vl[4];
                    uint32_t o = toff(tp * 16 + br, ks * 16 + bc);
                    ldsm4(vh, vh_b + o);
                    ldsm4(vl, vl_b + o);
                    mma16816(acc[2*tp],   ph, vh[0], vh[1]);
                    mma16816(acc[2*tp+1], ph, vh[2], vh[3]);
                    mma16816(acc[2*tp],   ph, vl[0], vl[1]);
                    mma16816(acc[2*tp+1], ph, vl[2], vl[3]);
                }
            }
        }
    }

    // ---- write a = acc, [c][q] layout ----
    #pragma unroll
    for (int t = 0; t < 8; t++) {
        int c = t * 8 + c2;
        float* a0 = ga + ((size_t)n * CH + c) * LQ + qbase + wrow;
        a0[qr]     = acc[t][0];
        a0[qr + 8] = acc[t][2];
        float* a1 = a0 + LQ;
        a1[qr]     = acc[t][1];
        a1[qr + 8] = acc[t][3];
    }
}

extern "C" void kernel_launch(void* const* d_in, const int* in_sizes, int n_in,
                              void* d_out, int out_size)
{
    const float* q = (const float*)d_in[0];
    const float* k = (const float*)d_in[1];
    const float* v = (const float*)d_in[2];
    const void*  mask = d_in[3];
    float* out = (float*)d_out;

    const long long A_ELEMS = (long long)NTOT * CH * LQ;   // 4,194,304
    const long long W_ELEMS = (long long)NTOT * LQ * LK;   // 134,217,728

    float* a_out;
    float* w_out;
    if ((long long)out_size >= A_ELEMS + W_ELEMS) {
        a_out = out;
        w_out = out + A_ELEMS;
    } else if ((long long)out_size >= W_ELEMS) {
        w_out = out;
        cudaGetSymbolAddress((void**)&a_out, g_a_scratch);
    } else {
        a_out = out;
        cudaGetSymbolAddress((void**)&w_out, g_w_scratch);
    }

    __half *q16, *k16h, *k16l, *v16h, *v16l;
    cudaGetSymbolAddress((void**)&q16,  g_q16);
    cudaGetSymbolAddress((void**)&k16h, g_k16h);
    cudaGetSymbolAddress((void**)&k16l, g_k16l);
    cudaGetSymbolAddress((void**)&v16h, g_v16h);
    cudaGetSymbolAddress((void**)&v16l, g_v16l);

    cudaFuncSetAttribute(attn_mma_kernel,
                         cudaFuncAttributeMaxDynamicSharedMemorySize, SMTOT);

    detect_mask_kind_kernel<<<1, 32>>>((const uint4*)mask);
    convert_kernel<<<dim3(32, NTOT, 3), 256>>>(q, k, v);

    dim3 grid(LQ / BQ, NTOT);
    attn_mma_kernel<<<grid, TPB, SMTOT>>>(q16, k16h, k16l, v16h, v16l,
                                          mask, a_out, w_out);
}